// round 5
// baseline (speedup 1.0000x reference)
#include <cuda_runtime.h>
#include <cuda_bf16.h>
#include <math.h>

// Problem constants
#define BATCH   4
#define SEQ     4096
#define CMODEL  2048
#define NHEAD   16
#define HDIM    128
#define NLAT    64
#define HL      (NHEAD * NLAT)     // 1024
#define SCALE_F (0.08838834764831845f) // 1/sqrt(128)

// ---------------- device scratch (no allocations allowed) ----------------
__device__ float g_k[BATCH * NLAT * CMODEL];            // k rows t<64:  [B,64,H,D] = 2MB
__device__ float g_v[BATCH * NLAT * CMODEL];            // v rows t<64
__device__ float g_attn[BATCH * NHEAD * NLAT * HDIM];   // [B,H,64,128] = 2MB
__device__ float g_P[(long long)BATCH * HL * CMODEL];   // [B, 1024, 2048] = 32MB
__device__ float g_gates[(long long)BATCH * SEQ * HL];  // [B*T, 1024] = 64MB

// ---------------- generic batched SGEMM (row-major, fp32) ----------------
// C[M,N] = A[M,K] @ B[K,N], lda=K, ldb=N, ldc=N.
// z-batch: Aoff = z*aStride, Boff = (bModulo? z%bModulo : z)*bStride, Coff = z*cStride
#define BM 128
#define BN 128
#define BKK 8
#define TM 8
#define TN 8

__global__ __launch_bounds__(256) void sgemm_batched(
    const float* __restrict__ A, const float* __restrict__ B, float* __restrict__ C,
    int M, int N, int K,
    long long aStride, long long bStride, long long cStride, int bModulo)
{
    int z = blockIdx.z;
    A += (long long)z * aStride;
    B += (long long)(bModulo > 0 ? (z % bModulo) : z) * bStride;
    C += (long long)z * cStride;

    __shared__ float As[BKK][BM];
    __shared__ float Bs[BKK][BN];

    const int tid = threadIdx.x;          // 256 threads
    const int blockRow = blockIdx.y * BM;
    const int blockCol = blockIdx.x * BN;
    const int tx = tid % (BN / TN);       // 0..15
    const int ty = tid / (BN / TN);       // 0..15

    float acc[TM][TN];
    #pragma unroll
    for (int i = 0; i < TM; i++)
        #pragma unroll
        for (int j = 0; j < TN; j++) acc[i][j] = 0.f;

    const int aRow  = tid / (BKK / 4);        // 0..127
    const int aCol4 = (tid % (BKK / 4)) * 4;  // 0 or 4
    const int bRow  = tid / (BN / 4);         // 0..7
    const int bCol4 = (tid % (BN / 4)) * 4;   // 0..124

    for (int k0 = 0; k0 < K; k0 += BKK) {
        // Load A tile (transposed into smem). Guard M (M may be 64).
        float4 av = make_float4(0.f, 0.f, 0.f, 0.f);
        int gRow = blockRow + aRow;
        if (gRow < M)
            av = *reinterpret_cast<const float4*>(&A[(long long)gRow * K + k0 + aCol4]);
        As[aCol4 + 0][aRow] = av.x;
        As[aCol4 + 1][aRow] = av.y;
        As[aCol4 + 2][aRow] = av.z;
        As[aCol4 + 3][aRow] = av.w;
        // Load B tile. N is always a multiple of 128, K multiple of 8.
        float4 bv = *reinterpret_cast<const float4*>(&B[(long long)(k0 + bRow) * N + blockCol + bCol4]);
        *reinterpret_cast<float4*>(&Bs[bRow][bCol4]) = bv;
        __syncthreads();

        #pragma unroll
        for (int kk = 0; kk < BKK; kk++) {
            float ra[TM], rb[TN];
            #pragma unroll
            for (int i = 0; i < TM; i++) ra[i] = As[kk][ty * TM + i];
            #pragma unroll
            for (int j = 0; j < TN; j++) rb[j] = Bs[kk][tx * TN + j];
            #pragma unroll
            for (int i = 0; i < TM; i++)
                #pragma unroll
                for (int j = 0; j < TN; j++)
                    acc[i][j] += ra[i] * rb[j];
        }
        __syncthreads();
    }

    #pragma unroll
    for (int i = 0; i < TM; i++) {
        int gRow = blockRow + ty * TM + i;
        if (gRow >= M) continue;
        #pragma unroll
        for (int j = 0; j < TN; j += 4) {
            float4 v = make_float4(acc[i][j], acc[i][j + 1], acc[i][j + 2], acc[i][j + 3]);
            *reinterpret_cast<float4*>(&C[(long long)gRow * N + blockCol + tx * TN + j]) = v;
        }
    }
}

// ---------------- RoPE on g_k : [B, 64, H, D], pairs (2i, 2i+1) ----------------
__global__ void rope_kernel(float* __restrict__ k)
{
    int idx = blockIdx.x * blockDim.x + threadIdx.x; // B*64*H*64 = 262144
    if (idx >= BATCH * NLAT * NHEAD * (HDIM / 2)) return;
    int i = idx & 63;
    int h = (idx >> 6) & 15;
    int t = (idx >> 10) & 63;
    int b = idx >> 16;
    // inv_freq = 10000^(-2i/128) = exp(-(2i/128)*ln(10000))
    float inv_freq = expf(-(2.0f * i / 128.0f) * 9.210340371976184f);
    float ang = (float)t * inv_freq;
    float c, s;
    __sincosf(ang, &s, &c);
    long long base = ((((long long)b * NLAT + t) * NHEAD + h) * HDIM) + 2 * i;
    float x0 = k[base], x1 = k[base + 1];
    k[base]     = x0 * c - x1 * s;
    k[base + 1] = x0 * s + x1 * c;
}

// ---------------- tiny causal attention over the first 64 positions ----------------
// one block per (b,h); attn[b,h,l,d] = sum_{t<=l} softmax(q_l . k_t * SCALE) * v[t,d]
__global__ __launch_bounds__(256) void attn_kernel(
    const float* __restrict__ lq,   // [64, 16, 128]  (latent_queries)
    const float* __restrict__ k,    // [B, 64, 16, 128]
    const float* __restrict__ v,    // [B, 64, 16, 128]
    float* __restrict__ attn)       // [B, 16, 64, 128]
{
    const int b = blockIdx.x >> 4;
    const int h = blockIdx.x & 15;
    const int tid = threadIdx.x;

    __shared__ float sS[NLAT * NLAT];     // 16KB scores/weights
    __shared__ float sV[NLAT * HDIM];     // 32KB V tile

    for (int i = tid; i < NLAT * HDIM; i += 256) {
        int t = i >> 7, d = i & 127;
        sV[i] = v[((((long long)b * NLAT + t) * NHEAD + h) * HDIM) + d];
    }

    // scores
    for (int i = tid; i < NLAT * NLAT; i += 256) {
        int l = i >> 6, t = i & 63;
        float s = -1e9f;
        if (t <= l) {
            const float* qp = lq + ((long long)l * NHEAD + h) * HDIM;
            const float* kp = k + (((long long)b * NLAT + t) * NHEAD + h) * HDIM;
            float acc = 0.f;
            #pragma unroll 4
            for (int d = 0; d < HDIM; d++) acc += qp[d] * kp[d];
            s = acc * SCALE_F;
        }
        sS[i] = s;
    }
    __syncthreads();

    // per-row softmax (rows = latents)
    if (tid < NLAT) {
        int l = tid;
        float m = -1e30f;
        for (int t = 0; t < NLAT; t++) m = fmaxf(m, sS[l * NLAT + t]);
        float sum = 0.f;
        for (int t = 0; t < NLAT; t++) {
            float e = __expf(sS[l * NLAT + t] - m);
            sS[l * NLAT + t] = e;
            sum += e;
        }
        float inv = 1.0f / sum;
        for (int t = 0; t < NLAT; t++) sS[l * NLAT + t] *= inv;
    }
    __syncthreads();

    // attn = W @ V
    for (int i = tid; i < NLAT * HDIM; i += 256) {
        int l = i >> 7, d = i & 127;
        float acc = 0.f;
        #pragma unroll 4
        for (int t = 0; t < NLAT; t++) acc += sS[l * NLAT + t] * sV[t * HDIM + d];
        attn[((((long long)b * NHEAD + h) * NLAT + l) * HDIM) + d] = acc;
    }
}

// ---------------- gate softmax: groups of 64 along last dim, times SCALE ----------------
__global__ void gate_softmax(float* __restrict__ g)
{
    // one warp per group of 64; total groups = B*T*H = 262144
    int gw = (blockIdx.x * blockDim.x + threadIdx.x) >> 5;
    int lane = threadIdx.x & 31;
    if (gw >= BATCH * SEQ * NHEAD) return;
    long long base = (long long)gw * 64;
    float v0 = g[base + lane] * SCALE_F;
    float v1 = g[base + 32 + lane] * SCALE_F;
    float m = fmaxf(v0, v1);
    #pragma unroll
    for (int o = 16; o; o >>= 1) m = fmaxf(m, __shfl_xor_sync(0xffffffffu, m, o));
    float e0 = __expf(v0 - m), e1 = __expf(v1 - m);
    float s = e0 + e1;
    #pragma unroll
    for (int o = 16; o; o >>= 1) s += __shfl_xor_sync(0xffffffffu, s, o);
    float inv = 1.0f / s;
    g[base + lane] = e0 * inv;
    g[base + 32 + lane] = e1 * inv;
}

// ---------------- launch ----------------
extern "C" void kernel_launch(void* const* d_in, const int* in_sizes, int n_in,
                              void* d_out, int out_size)
{
    const float* x  = (const float*)d_in[0];  // [4,4096,2048]
    const float* lq = (const float*)d_in[1];  // [1,64,16,128]
    const float* Wk = (const float*)d_in[2];  // [2048,2048]
    const float* Wv = (const float*)d_in[3];
    const float* Wg = (const float*)d_in[4];  // [2048,1024]
    const float* Wp = (const float*)d_in[5];  // [2048,2048]
    float* out = (float*)d_out;               // [4,4096,2048]

    float *kbuf, *vbuf, *attnbuf, *Pbuf, *gatesbuf;
    cudaGetSymbolAddress((void**)&kbuf, g_k);
    cudaGetSymbolAddress((void**)&vbuf, g_v);
    cudaGetSymbolAddress((void**)&attnbuf, g_attn);
    cudaGetSymbolAddress((void**)&Pbuf, g_P);
    cudaGetSymbolAddress((void**)&gatesbuf, g_gates);

    // 1) k = x[:, :64] @ Wk ; v = x[:, :64] @ Wv   (batched over B)
    {
        dim3 grid(CMODEL / BN, (NLAT + BM - 1) / BM, BATCH);
        sgemm_batched<<<grid, 256>>>(x, Wk, kbuf, NLAT, CMODEL, CMODEL,
                                     (long long)SEQ * CMODEL, 0LL,
                                     (long long)NLAT * CMODEL, 1);
        sgemm_batched<<<grid, 256>>>(x, Wv, vbuf, NLAT, CMODEL, CMODEL,
                                     (long long)SEQ * CMODEL, 0LL,
                                     (long long)NLAT * CMODEL, 1);
    }

    // 2) RoPE on k (positions 0..63)
    rope_kernel<<<(BATCH * NLAT * NHEAD * (HDIM / 2) + 255) / 256, 256>>>(kbuf);

    // 3) attention -> attn [B,H,64,128]
    attn_kernel<<<BATCH * NHEAD, 256>>>(lq, kbuf, vbuf, attnbuf);

    // 4) P[b,h,l,:] = attn[b,h,l,:] @ Wp[h*128:(h+1)*128, :]   (batched over b*h)
    {
        dim3 grid(CMODEL / BN, 1, BATCH * NHEAD);
        sgemm_batched<<<grid, 256>>>(attnbuf, Wp, Pbuf, NLAT, CMODEL, HDIM,
                                     (long long)NLAT * HDIM,
                                     (long long)HDIM * CMODEL,
                                     (long long)NLAT * CMODEL, NHEAD);
    }

    // 5) gates = x @ Wg  ([16384,2048]@[2048,1024]) then softmax(SCALE*.) per 64-group
    {
        dim3 grid(HL / BN, (BATCH * SEQ) / BM, 1);
        sgemm_batched<<<grid, 256>>>(x, Wg, gatesbuf, BATCH * SEQ, HL, CMODEL,
                                     0LL, 0LL, 0LL, 1);
    }
    gate_softmax<<<(BATCH * SEQ * NHEAD * 32 + 255) / 256, 256>>>(gatesbuf);

    // 6) out[b] = gates[b] [4096,1024] @ P[b] [1024,2048]
    {
        dim3 grid(CMODEL / BN, SEQ / BM, BATCH);
        sgemm_batched<<<grid, 256>>>(gatesbuf, Pbuf, out, SEQ, CMODEL, HL,
                                     (long long)SEQ * HL,
                                     (long long)HL * CMODEL,
                                     (long long)SEQ * CMODEL, 0);
    }
}

// round 7
// speedup vs baseline: 1.0560x; 1.0560x over previous
#include <cuda_runtime.h>
#include <cuda_bf16.h>
#include <math.h>

// Problem constants
#define BATCH   4
#define SEQ     4096
#define CMODEL  2048
#define NHEAD   16
#define HDIM    128
#define NLAT    64
#define HL      (NHEAD * NLAT)     // 1024
#define SCALE_F (0.08838834764831845f) // 1/sqrt(128)

// ---------------- device scratch (no allocations allowed) ----------------
__device__ float g_k[BATCH * NLAT * CMODEL];            // k rows t<64:  [B,64,H,D] = 2MB
__device__ float g_v[BATCH * NLAT * CMODEL];            // v rows t<64
__device__ float g_attn[BATCH * NHEAD * NLAT * HDIM];   // [B,H,64,128] = 2MB
__device__ float g_P[(long long)BATCH * HL * CMODEL];   // [B, 1024, 2048] = 32MB
__device__ float g_gates[(long long)BATCH * SEQ * HL];  // [B*T, 1024] = 64MB

// ---------------- generic batched SGEMM (row-major, fp32) ----------------
// C[M,N] = A[M,K] @ B[K,N], lda=K, ldb=N, ldc=N.
// z-batch: Aoff = z*aStride, Boff = (bModulo? z%bModulo : z)*bStride, Coff = z*cStride
#define BM 128
#define BN 128
#define BKK 8
#define TM 8
#define TN 8

__global__ __launch_bounds__(256) void sgemm_batched(
    const float* __restrict__ A, const float* __restrict__ B, float* __restrict__ C,
    int M, int N, int K,
    long long aStride, long long bStride, long long cStride, int bModulo)
{
    int z = blockIdx.z;
    A += (long long)z * aStride;
    B += (long long)(bModulo > 0 ? (z % bModulo) : z) * bStride;
    C += (long long)z * cStride;

    __shared__ float As[BKK][BM];
    __shared__ float Bs[BKK][BN];

    const int tid = threadIdx.x;          // 256 threads
    const int blockRow = blockIdx.y * BM;
    const int blockCol = blockIdx.x * BN;
    const int tx = tid % (BN / TN);       // 0..15
    const int ty = tid / (BN / TN);       // 0..15

    float acc[TM][TN];
    #pragma unroll
    for (int i = 0; i < TM; i++)
        #pragma unroll
        for (int j = 0; j < TN; j++) acc[i][j] = 0.f;

    const int aRow  = tid / (BKK / 4);        // 0..127
    const int aCol4 = (tid % (BKK / 4)) * 4;  // 0 or 4
    const int bRow  = tid / (BN / 4);         // 0..7
    const int bCol4 = (tid % (BN / 4)) * 4;   // 0..124

    for (int k0 = 0; k0 < K; k0 += BKK) {
        // Load A tile (transposed into smem). Guard M (M may be 64).
        float4 av = make_float4(0.f, 0.f, 0.f, 0.f);
        int gRow = blockRow + aRow;
        if (gRow < M)
            av = *reinterpret_cast<const float4*>(&A[(long long)gRow * K + k0 + aCol4]);
        As[aCol4 + 0][aRow] = av.x;
        As[aCol4 + 1][aRow] = av.y;
        As[aCol4 + 2][aRow] = av.z;
        As[aCol4 + 3][aRow] = av.w;
        // Load B tile. N is always a multiple of 128, K multiple of 8.
        float4 bv = *reinterpret_cast<const float4*>(&B[(long long)(k0 + bRow) * N + blockCol + bCol4]);
        *reinterpret_cast<float4*>(&Bs[bRow][bCol4]) = bv;
        __syncthreads();

        #pragma unroll
        for (int kk = 0; kk < BKK; kk++) {
            float ra[TM], rb[TN];
            #pragma unroll
            for (int i = 0; i < TM; i++) ra[i] = As[kk][ty * TM + i];
            #pragma unroll
            for (int j = 0; j < TN; j++) rb[j] = Bs[kk][tx * TN + j];
            #pragma unroll
            for (int i = 0; i < TM; i++)
                #pragma unroll
                for (int j = 0; j < TN; j++)
                    acc[i][j] += ra[i] * rb[j];
        }
        __syncthreads();
    }

    #pragma unroll
    for (int i = 0; i < TM; i++) {
        int gRow = blockRow + ty * TM + i;
        if (gRow >= M) continue;
        #pragma unroll
        for (int j = 0; j < TN; j += 4) {
            float4 v = make_float4(acc[i][j], acc[i][j + 1], acc[i][j + 2], acc[i][j + 3]);
            *reinterpret_cast<float4*>(&C[(long long)gRow * N + blockCol + tx * TN + j]) = v;
        }
    }
}

// ---------------- RoPE on g_k : [B, 64, H, D], pairs (2i, 2i+1) ----------------
__global__ void rope_kernel(float* __restrict__ k)
{
    int idx = blockIdx.x * blockDim.x + threadIdx.x; // B*64*H*64 = 262144
    if (idx >= BATCH * NLAT * NHEAD * (HDIM / 2)) return;
    int i = idx & 63;
    int h = (idx >> 6) & 15;
    int t = (idx >> 10) & 63;
    int b = idx >> 16;
    // inv_freq = 10000^(-2i/128) = exp(-(2i/128)*ln(10000))
    float inv_freq = expf(-(2.0f * i / 128.0f) * 9.210340371976184f);
    float ang = (float)t * inv_freq;
    float c, s;
    __sincosf(ang, &s, &c);
    long long base = ((((long long)b * NLAT + t) * NHEAD + h) * HDIM) + 2 * i;
    float x0 = k[base], x1 = k[base + 1];
    k[base]     = x0 * c - x1 * s;
    k[base + 1] = x0 * s + x1 * c;
}

// ---------------- tiny causal attention over the first 64 positions ----------------
// one block per (b,h); attn[b,h,l,d] = sum_{t<=l} softmax(q_l . k_t * SCALE) * v[t,d]
__global__ __launch_bounds__(256) void attn_kernel(
    const float* __restrict__ lq,   // [64, 16, 128]  (latent_queries)
    const float* __restrict__ k,    // [B, 64, 16, 128]
    const float* __restrict__ v,    // [B, 64, 16, 128]
    float* __restrict__ attn)       // [B, 16, 64, 128]
{
    const int b = blockIdx.x >> 4;
    const int h = blockIdx.x & 15;
    const int tid = threadIdx.x;

    __shared__ float sS[NLAT * NLAT];     // 16KB scores/weights
    __shared__ float sV[NLAT * HDIM];     // 32KB V tile

    for (int i = tid; i < NLAT * HDIM; i += 256) {
        int t = i >> 7, d = i & 127;
        sV[i] = v[((((long long)b * NLAT + t) * NHEAD + h) * HDIM) + d];
    }

    // scores
    for (int i = tid; i < NLAT * NLAT; i += 256) {
        int l = i >> 6, t = i & 63;
        float s = -1e9f;
        if (t <= l) {
            const float* qp = lq + ((long long)l * NHEAD + h) * HDIM;
            const float* kp = k + (((long long)b * NLAT + t) * NHEAD + h) * HDIM;
            float acc = 0.f;
            #pragma unroll 4
            for (int d = 0; d < HDIM; d++) acc += qp[d] * kp[d];
            s = acc * SCALE_F;
        }
        sS[i] = s;
    }
    __syncthreads();

    // per-row softmax (rows = latents)
    if (tid < NLAT) {
        int l = tid;
        float m = -1e30f;
        for (int t = 0; t < NLAT; t++) m = fmaxf(m, sS[l * NLAT + t]);
        float sum = 0.f;
        for (int t = 0; t < NLAT; t++) {
            float e = __expf(sS[l * NLAT + t] - m);
            sS[l * NLAT + t] = e;
            sum += e;
        }
        float inv = 1.0f / sum;
        for (int t = 0; t < NLAT; t++) sS[l * NLAT + t] *= inv;
    }
    __syncthreads();

    // attn = W @ V
    for (int i = tid; i < NLAT * HDIM; i += 256) {
        int l = i >> 7, d = i & 127;
        float acc = 0.f;
        #pragma unroll 4
        for (int t = 0; t < NLAT; t++) acc += sS[l * NLAT + t] * sV[t * HDIM + d];
        attn[((((long long)b * NHEAD + h) * NLAT + l) * HDIM) + d] = acc;
    }
}

// ---------------- gate softmax: groups of 64 along last dim, times SCALE ----------------
__global__ void gate_softmax(float* __restrict__ g)
{
    // one warp per group of 64; total groups = B*T*H = 262144
    int gw = (blockIdx.x * blockDim.x + threadIdx.x) >> 5;
    int lane = threadIdx.x & 31;
    if (gw >= BATCH * SEQ * NHEAD) return;
    long long base = (long long)gw * 64;
    float v0 = g[base + lane] * SCALE_F;
    float v1 = g[base + 32 + lane] * SCALE_F;
    float m = fmaxf(v0, v1);
    #pragma unroll
    for (int o = 16; o; o >>= 1) m = fmaxf(m, __shfl_xor_sync(0xffffffffu, m, o));
    float e0 = __expf(v0 - m), e1 = __expf(v1 - m);
    float s = e0 + e1;
    #pragma unroll
    for (int o = 16; o; o >>= 1) s += __shfl_xor_sync(0xffffffffu, s, o);
    float inv = 1.0f / s;
    g[base + lane] = e0 * inv;
    g[base + 32 + lane] = e1 * inv;
}

// ---------------- launch ----------------
extern "C" void kernel_launch(void* const* d_in, const int* in_sizes, int n_in,
                              void* d_out, int out_size)
{
    const float* x  = (const float*)d_in[0];  // [4,4096,2048]
    const float* lq = (const float*)d_in[1];  // [1,64,16,128]
    const float* Wk = (const float*)d_in[2];  // [2048,2048]
    const float* Wv = (const float*)d_in[3];
    const float* Wg = (const float*)d_in[4];  // [2048,1024]
    const float* Wp = (const float*)d_in[5];  // [2048,2048]
    float* out = (float*)d_out;               // [4,4096,2048]

    float *kbuf, *vbuf, *attnbuf, *Pbuf, *gatesbuf;
    cudaGetSymbolAddress((void**)&kbuf, g_k);
    cudaGetSymbolAddress((void**)&vbuf, g_v);
    cudaGetSymbolAddress((void**)&attnbuf, g_attn);
    cudaGetSymbolAddress((void**)&Pbuf, g_P);
    cudaGetSymbolAddress((void**)&gatesbuf, g_gates);

    // 1) k = x[:, :64] @ Wk ; v = x[:, :64] @ Wv   (batched over B)
    {
        dim3 grid(CMODEL / BN, (NLAT + BM - 1) / BM, BATCH);
        sgemm_batched<<<grid, 256>>>(x, Wk, kbuf, NLAT, CMODEL, CMODEL,
                                     (long long)SEQ * CMODEL, 0LL,
                                     (long long)NLAT * CMODEL, 1);
        sgemm_batched<<<grid, 256>>>(x, Wv, vbuf, NLAT, CMODEL, CMODEL,
                                     (long long)SEQ * CMODEL, 0LL,
                                     (long long)NLAT * CMODEL, 1);
    }

    // 2) RoPE on k (positions 0..63)
    rope_kernel<<<(BATCH * NLAT * NHEAD * (HDIM / 2) + 255) / 256, 256>>>(kbuf);

    // 3) attention -> attn [B,H,64,128]
    attn_kernel<<<BATCH * NHEAD, 256>>>(lq, kbuf, vbuf, attnbuf);

    // 4) P[b,h,l,:] = attn[b,h,l,:] @ Wp[h*128:(h+1)*128, :]   (batched over b*h)
    {
        dim3 grid(CMODEL / BN, 1, BATCH * NHEAD);
        sgemm_batched<<<grid, 256>>>(attnbuf, Wp, Pbuf, NLAT, CMODEL, HDIM,
                                     (long long)NLAT * HDIM,
                                     (long long)HDIM * CMODEL,
                                     (long long)NLAT * CMODEL, NHEAD);
    }

    // 5) gates = x @ Wg  ([16384,2048]@[2048,1024]) then softmax(SCALE*.) per 64-group
    {
        dim3 grid(HL / BN, (BATCH * SEQ) / BM, 1);
        sgemm_batched<<<grid, 256>>>(x, Wg, gatesbuf, BATCH * SEQ, HL, CMODEL,
                                     0LL, 0LL, 0LL, 1);
    }
    gate_softmax<<<(BATCH * SEQ * NHEAD * 32 + 255) / 256, 256>>>(gatesbuf);

    // 6) out[b] = gates[b] [4096,1024] @ P[b] [1024,2048]
    {
        dim3 grid(CMODEL / BN, SEQ / BM, BATCH);
        sgemm_batched<<<grid, 256>>>(gatesbuf, Pbuf, out, SEQ, CMODEL, HL,
                                     (long long)SEQ * HL,
                                     (long long)HL * CMODEL,
                                     (long long)SEQ * CMODEL, 0);
    }
}

// round 10
// speedup vs baseline: 3.7430x; 3.5445x over previous
#include <cuda_runtime.h>
#include <cuda_bf16.h>
#include <cstdint>
#include <math.h>

#define BATCH 4
#define SEQ 4096
#define CM 2048
#define NHEAD 16
#define HDIM 128
#define NLAT 64
#define HL 1024
#define SCALE_F 0.08838834764831845f

typedef __nv_bfloat16 bf16;

// ------------------- device scratch (no allocations allowed) -------------------
__device__ bf16 g_Xh[(size_t)16384 * 2048];
__device__ bf16 g_Xl[(size_t)16384 * 2048];
__device__ bf16 g_Wkt_h[(size_t)2048 * 2048];
__device__ bf16 g_Wkt_l[(size_t)2048 * 2048];
__device__ bf16 g_Wvt_h[(size_t)2048 * 2048];
__device__ bf16 g_Wvt_l[(size_t)2048 * 2048];
__device__ bf16 g_Wpt_h[(size_t)2048 * 2048];
__device__ bf16 g_Wpt_l[(size_t)2048 * 2048];
__device__ bf16 g_Wgt_h[(size_t)1024 * 2048];
__device__ bf16 g_Wgt_l[(size_t)1024 * 2048];
__device__ float g_k[BATCH * NLAT * CM];
__device__ float g_v[BATCH * NLAT * CM];
__device__ bf16 g_ah[BATCH * NHEAD * NLAT * HDIM];
__device__ bf16 g_al[BATCH * NHEAD * NLAT * HDIM];
__device__ float g_P[(size_t)BATCH * HL * CM];
__device__ bf16 g_Pth[(size_t)BATCH * CM * HL];
__device__ bf16 g_Ptl[(size_t)BATCH * CM * HL];
__device__ bf16 g_Gh[(size_t)16384 * 1024];
__device__ bf16 g_Gl[(size_t)16384 * 1024];

// ------------------- helpers (baseline PTX only: sm_80-era ops) -------------------
__device__ __forceinline__ uint32_t smem_u32(const void* p) {
    uint32_t a;
    asm("{ .reg .u64 t; cvta.to.shared.u64 t, %1; cvt.u32.u64 %0, t; }" : "=r"(a) : "l"(p));
    return a;
}
__device__ __forceinline__ void cpa16(uint32_t sdst, const void* gsrc) {
    asm volatile("cp.async.cg.shared.global [%0], [%1], 16;" :: "r"(sdst), "l"(gsrc));
}
#define CP_COMMIT() asm volatile("cp.async.commit_group;" ::: "memory")
#define CP_WAIT1()  asm volatile("cp.async.wait_group 1;" ::: "memory")
#define CP_WAIT0()  asm volatile("cp.async.wait_group 0;" ::: "memory")

__device__ __forceinline__ void ldsm4(uint32_t* r, uint32_t addr) {
    asm volatile("ldmatrix.sync.aligned.m8n8.x4.shared.b16 {%0,%1,%2,%3}, [%4];"
                 : "=r"(r[0]), "=r"(r[1]), "=r"(r[2]), "=r"(r[3]) : "r"(addr));
}
__device__ __forceinline__ void mma16816(float* c, const uint32_t* a, const uint32_t* b) {
    asm volatile(
        "mma.sync.aligned.m16n8k16.row.col.f32.bf16.bf16.f32 "
        "{%0,%1,%2,%3}, {%4,%5,%6,%7}, {%8,%9}, {%0,%1,%2,%3};"
        : "+f"(c[0]), "+f"(c[1]), "+f"(c[2]), "+f"(c[3])
        : "r"(a[0]), "r"(a[1]), "r"(a[2]), "r"(a[3]), "r"(b[0]), "r"(b[1]));
}
__device__ __forceinline__ uint32_t swz(uint32_t off) { return off ^ ((off >> 3) & 0x70); }

// =================== split-bf16 warp-MMA GEMM ===================
// C[M,N] = (Ah+Al)[M,K] @ (Bh+Bl)[N,K]^T   (B stored [N,K] row-major)
// MODE 0: fp32 C (row-guarded via clamp+store-guard).
// MODE 2: fused 64-group softmax(*SCALE) -> Ch/Cl bf16 hi/lo.
// Tile: BM=BN=128, BK=64; 256 threads = 8 warps as 2(M) x 4(N); warp tile 64x32.
#define STAGE_BYTES 65536              // Ah(16K) Al(16K) Bh(16K) Bl(16K)
#define MM_SMEM (2 * STAGE_BYTES)      // 128 KB; epilogue fp32[128][129] aliases

template <int MODE>
__global__ __launch_bounds__(256, 1)
void mm_tc(const bf16* __restrict__ Ah, const bf16* __restrict__ Al,
           const bf16* __restrict__ Bh, const bf16* __restrict__ Bl,
           float* __restrict__ C, bf16* __restrict__ Ch, bf16* __restrict__ Cl,
           int M, int K, int lda, int ldb, int ldc,
           long long aStride, long long bStride, long long cStride, int bModulo)
{
    extern __shared__ char smem[];
    const uint32_t sb = smem_u32(smem);

    const int tid = threadIdx.x;
    const int wid = tid >> 5, lane = tid & 31;
    const int warpM = wid >> 2;        // 0..1  (64-row slab)
    const int warpN = wid & 3;         // 0..3  (32-col slab)
    const int z = blockIdx.z;
    const int rowBase = blockIdx.y * 128;
    const int colBase = blockIdx.x * 128;

    Ah += (long long)z * aStride;
    Al += (long long)z * aStride;
    const long long bo = (long long)(bModulo > 0 ? (z % bModulo) : z) * bStride;
    Bh += bo; Bl += bo;
    const long long co = (long long)z * cStride;

    // precomputed per-thread staging coords: 4 rounds x (r,u)
    int sr[4], su[4];
    #pragma unroll
    for (int i = 0; i < 4; i++) {
        const int q = (i << 8) + tid;  // 0..1023
        sr[i] = q >> 3;                // 0..127
        su[i] = q & 7;                 // 16B unit 0..7
    }

    float acc[4][4][4];
    #pragma unroll
    for (int mi = 0; mi < 4; mi++)
        #pragma unroll
        for (int ni = 0; ni < 4; ni++)
            #pragma unroll
            for (int e = 0; e < 4; e++) acc[mi][ni][e] = 0.f;

    const int nC = K >> 6;

    // ---- issue stage c into buffer c&1 ----
    auto issue = [&](int c) {
        const int k0 = c << 6;
        const uint32_t st = sb + (uint32_t)(c & 1) * STAGE_BYTES;
        #pragma unroll
        for (int i = 0; i < 4; i++) {
            const int r = sr[i];
            const uint32_t so = swz((uint32_t)(r * 128 + su[i] * 16));
            const int kk = k0 + su[i] * 8;
            int ga = rowBase + r; if (ga >= M) ga = M - 1;   // clamp (finite garbage, never stored)
            const int gb = colBase + r;
            cpa16(st + so,          Ah + (size_t)ga * lda + kk);
            cpa16(st + 16384 + so,  Al + (size_t)ga * lda + kk);
            cpa16(st + 32768 + so,  Bh + (size_t)gb * ldb + kk);
            cpa16(st + 49152 + so,  Bl + (size_t)gb * ldb + kk);
        }
        CP_COMMIT();
    };

    issue(0);
    for (int c = 0; c < nC; c++) {
        const bool more = (c + 1 < nC);
        if (more) issue(c + 1);
        if (more) CP_WAIT1(); else CP_WAIT0();
        __syncthreads();

        const uint32_t st = sb + (uint32_t)(c & 1) * STAGE_BYTES;
        const uint32_t sAh = st, sAl = st + 16384, sBh = st + 32768, sBl = st + 49152;

        // per-lane ldmatrix address pieces
        const int aRow16 = lane & 15;              // row within 16-row A frag
        const int aUhalf = lane >> 4;              // 0/1 -> k lo/hi unit
        const int bRow   = ((lane >> 4) & 1) * 8 + (lane & 7);  // row within 16-n B block
        const int bUhalf = (lane >> 3) & 1;        // 0/1 -> k lo/hi unit

        #pragma unroll
        for (int ks = 0; ks < 4; ks++) {
            uint32_t ah[4][4], al[4][4];
            #pragma unroll
            for (int mi = 0; mi < 4; mi++) {
                const int row = warpM * 64 + mi * 16 + aRow16;
                const uint32_t off = swz((uint32_t)(row * 128 + (ks * 2 + aUhalf) * 16));
                ldsm4(ah[mi], sAh + off);
                ldsm4(al[mi], sAl + off);
            }
            uint32_t bh[4][2], bl[4][2];
            #pragma unroll
            for (int nb = 0; nb < 2; nb++) {
                const int row = warpN * 32 + nb * 16 + bRow;
                const uint32_t off = swz((uint32_t)(row * 128 + (ks * 2 + bUhalf) * 16));
                uint32_t t[4];
                ldsm4(t, sBh + off);
                bh[nb * 2][0] = t[0]; bh[nb * 2][1] = t[1];
                bh[nb * 2 + 1][0] = t[2]; bh[nb * 2 + 1][1] = t[3];
                ldsm4(t, sBl + off);
                bl[nb * 2][0] = t[0]; bl[nb * 2][1] = t[1];
                bl[nb * 2 + 1][0] = t[2]; bl[nb * 2 + 1][1] = t[3];
            }
            #pragma unroll
            for (int mi = 0; mi < 4; mi++)
                #pragma unroll
                for (int ni = 0; ni < 4; ni++) {
                    mma16816(acc[mi][ni], ah[mi], bh[ni]);  // Ah*Bh
                    mma16816(acc[mi][ni], al[mi], bh[ni]);  // Al*Bh
                    mma16816(acc[mi][ni], ah[mi], bl[ni]);  // Ah*Bl
                }
        }
        __syncthreads();   // protect buffer reuse by issue(c+2)
    }

    const int lr = lane >> 2;          // 0..7
    const int lc = (lane & 3) * 2;     // 0,2,4,6

    if (MODE == 0) {
        #pragma unroll
        for (int mi = 0; mi < 4; mi++)
            #pragma unroll
            for (int ni = 0; ni < 4; ni++) {
                const int r0 = rowBase + warpM * 64 + mi * 16 + lr;
                const int cc = colBase + warpN * 32 + ni * 8 + lc;
                if (r0 < M)
                    *reinterpret_cast<float2*>(&C[co + (size_t)r0 * ldc + cc]) =
                        make_float2(acc[mi][ni][0], acc[mi][ni][1]);
                if (r0 + 8 < M)
                    *reinterpret_cast<float2*>(&C[co + (size_t)(r0 + 8) * ldc + cc]) =
                        make_float2(acc[mi][ni][2], acc[mi][ni][3]);
            }
    } else {
        float* es = reinterpret_cast<float*>(smem);   // 128 x 129 fp32 (aliases stages; synced)
        #pragma unroll
        for (int mi = 0; mi < 4; mi++)
            #pragma unroll
            for (int ni = 0; ni < 4; ni++) {
                const int r0 = warpM * 64 + mi * 16 + lr;
                const int cc = warpN * 32 + ni * 8 + lc;
                es[r0 * 129 + cc]       = acc[mi][ni][0];
                es[r0 * 129 + cc + 1]   = acc[mi][ni][1];
                es[(r0 + 8) * 129 + cc]     = acc[mi][ni][2];
                es[(r0 + 8) * 129 + cc + 1] = acc[mi][ni][3];
            }
        __syncthreads();
        {   // 64-group softmax: 256 threads = 128 rows x 2 groups
            const int r = tid & 127, g = tid >> 7;
            float* p = es + r * 129 + g * 64;
            float m = -1e30f;
            #pragma unroll 4
            for (int i = 0; i < 64; i++) m = fmaxf(m, p[i] * SCALE_F);
            float s = 0.f;
            #pragma unroll 4
            for (int i = 0; i < 64; i++) { float e = __expf(p[i] * SCALE_F - m); p[i] = e; s += e; }
            const float inv = 1.0f / s;
            #pragma unroll 4
            for (int i = 0; i < 64; i++) p[i] *= inv;
        }
        __syncthreads();
        for (int idx = tid; idx < 16384; idx += 256) {
            const int r = idx >> 7, cc = idx & 127;
            const float v = es[r * 129 + cc];
            const bf16 h = __float2bfloat16(v);
            const bf16 l = __float2bfloat16(v - __bfloat162float(h));
            const size_t o = (size_t)(rowBase + r) * ldc + colBase + cc;
            Ch[o] = h; Cl[o] = l;
        }
    }
}

// =================== elementwise split ===================
__global__ void fsplit(const float* __restrict__ src, bf16* __restrict__ h,
                       bf16* __restrict__ l, size_t n)
{
    size_t i = ((size_t)blockIdx.x * blockDim.x + threadIdx.x) * 4;
    if (i >= n) return;
    float4 v = *reinterpret_cast<const float4*>(src + i);
    bf16 h0 = __float2bfloat16(v.x), h1 = __float2bfloat16(v.y);
    bf16 h2 = __float2bfloat16(v.z), h3 = __float2bfloat16(v.w);
    bf16 l0 = __float2bfloat16(v.x - __bfloat162float(h0));
    bf16 l1 = __float2bfloat16(v.y - __bfloat162float(h1));
    bf16 l2 = __float2bfloat16(v.z - __bfloat162float(h2));
    bf16 l3 = __float2bfloat16(v.w - __bfloat162float(h3));
    uint2 hp, lp;
    hp.x = (uint32_t)__bfloat16_as_ushort(h0) | ((uint32_t)__bfloat16_as_ushort(h1) << 16);
    hp.y = (uint32_t)__bfloat16_as_ushort(h2) | ((uint32_t)__bfloat16_as_ushort(h3) << 16);
    lp.x = (uint32_t)__bfloat16_as_ushort(l0) | ((uint32_t)__bfloat16_as_ushort(l1) << 16);
    lp.y = (uint32_t)__bfloat16_as_ushort(l2) | ((uint32_t)__bfloat16_as_ushort(l3) << 16);
    *reinterpret_cast<uint2*>(h + i) = hp;
    *reinterpret_cast<uint2*>(l + i) = lp;
}

// =================== transpose + split: src[R,C] fp32 -> dst[C,R] bf16 hi/lo ===================
__global__ void tsplit(const float* __restrict__ src, bf16* __restrict__ dh,
                       bf16* __restrict__ dl, int R, int C,
                       long long sStride, long long dStride)
{
    __shared__ float t[32][33];
    const int z = blockIdx.z;
    src += (long long)z * sStride;
    dh += (long long)z * dStride;
    dl += (long long)z * dStride;
    const int c0 = blockIdx.x * 32, r0 = blockIdx.y * 32;
    const int x = threadIdx.x, y = threadIdx.y;   // 32 x 8
    #pragma unroll
    for (int j = 0; j < 32; j += 8)
        t[y + j][x] = src[(size_t)(r0 + y + j) * C + c0 + x];
    __syncthreads();
    #pragma unroll
    for (int j = 0; j < 32; j += 8) {
        const float v = t[x][y + j];
        const bf16 h = __float2bfloat16(v);
        const bf16 l = __float2bfloat16(v - __bfloat162float(h));
        const size_t o = (size_t)(c0 + y + j) * R + r0 + x;
        dh[o] = h; dl[o] = l;
    }
}

// =================== RoPE on g_k : [B, 64, H, D] fp32 ===================
__global__ void rope_kernel(float* __restrict__ k)
{
    int idx = blockIdx.x * blockDim.x + threadIdx.x;
    if (idx >= BATCH * NLAT * NHEAD * (HDIM / 2)) return;
    const int i = idx & 63;
    const int h = (idx >> 6) & 15;
    const int t = (idx >> 10) & 63;
    const int b = idx >> 16;
    const float inv_freq = expf(-(2.0f * i / 128.0f) * 9.210340371976184f);
    float s, c;
    __sincosf((float)t * inv_freq, &s, &c);
    const size_t base = ((((size_t)b * NLAT + t) * NHEAD + h) * HDIM) + 2 * i;
    const float x0 = k[base], x1 = k[base + 1];
    k[base]     = x0 * c - x1 * s;
    k[base + 1] = x0 * s + x1 * c;
}

// =================== small causal attention, outputs bf16 hi/lo ===================
#define ATTN_SMEM ((8192 + 64*129 + 64*129 + 64*65) * 4)
__global__ __launch_bounds__(256, 1) void attn2(
    const float* __restrict__ lq, const float* __restrict__ k, const float* __restrict__ v,
    bf16* __restrict__ ah, bf16* __restrict__ al)
{
    extern __shared__ float s[];
    float* sQ = s;               // 64*128
    float* sK = s + 8192;        // 64*129 (padded)
    float* sV = sK + 64 * 129;   // 64*129
    float* sS = sV + 64 * 129;   // 64*65
    const int b = blockIdx.x >> 4, h = blockIdx.x & 15;
    const int tid = threadIdx.x;

    for (int i = tid; i < 8192; i += 256) {
        const int t = i >> 7, d = i & 127;
        sQ[i] = lq[(t * 16 + h) * 128 + d];
        const size_t gi = (((size_t)(b * 64 + t)) * 16 + h) * 128 + d;
        sK[t * 129 + d] = k[gi];
        sV[t * 129 + d] = v[gi];
    }
    __syncthreads();

    for (int i = tid; i < 4096; i += 256) {
        const int l = i >> 6, t = i & 63;
        float sc = -1e9f;
        if (t <= l) {
            const float* qp = sQ + l * 128;
            const float* kp = sK + t * 129;
            float a0 = 0.f, a1 = 0.f, a2 = 0.f, a3 = 0.f;
            #pragma unroll
            for (int d = 0; d < 128; d += 4) {
                a0 += qp[d] * kp[d];         a1 += qp[d + 1] * kp[d + 1];
                a2 += qp[d + 2] * kp[d + 2]; a3 += qp[d + 3] * kp[d + 3];
            }
            sc = (a0 + a1 + a2 + a3) * SCALE_F;
        }
        sS[l * 65 + t] = sc;
    }
    __syncthreads();

    if (tid < 64) {
        float* p = sS + tid * 65;
        float m = -1e30f;
        for (int t = 0; t < 64; t++) m = fmaxf(m, p[t]);
        float sum = 0.f;
        for (int t = 0; t < 64; t++) { float e = __expf(p[t] - m); p[t] = e; sum += e; }
        const float inv = 1.0f / sum;
        for (int t = 0; t < 64; t++) p[t] *= inv;
    }
    __syncthreads();

    for (int i = tid; i < 8192; i += 256) {
        const int l = i >> 7, d = i & 127;
        const float* w = sS + l * 65;
        float a0 = 0.f, a1 = 0.f, a2 = 0.f, a3 = 0.f;
        #pragma unroll
        for (int t = 0; t < 64; t += 4) {
            a0 += w[t] * sV[t * 129 + d];
            a1 += w[t + 1] * sV[(t + 1) * 129 + d];
            a2 += w[t + 2] * sV[(t + 2) * 129 + d];
            a3 += w[t + 3] * sV[(t + 3) * 129 + d];
        }
        const float acc = a0 + a1 + a2 + a3;
        const size_t o = ((size_t)(b * 16 + h) * 64 + l) * 128 + d;
        const bf16 hh = __float2bfloat16(acc);
        ah[o] = hh;
        al[o] = __float2bfloat16(acc - __bfloat162float(hh));
    }
}

// =================== launch ===================
extern "C" void kernel_launch(void* const* d_in, const int* in_sizes, int n_in,
                              void* d_out, int out_size)
{
    const float* x  = (const float*)d_in[0];
    const float* lq = (const float*)d_in[1];
    const float* Wk = (const float*)d_in[2];
    const float* Wv = (const float*)d_in[3];
    const float* Wg = (const float*)d_in[4];
    const float* Wp = (const float*)d_in[5];
    float* out = (float*)d_out;

    bf16 *Xh, *Xl, *Wkth, *Wktl, *Wvth, *Wvtl, *Wpth, *Wptl, *Wgth, *Wgtl;
    bf16 *ah, *al, *Pth, *Ptl, *Gh, *Gl;
    float *kb, *vb, *Pb;
    cudaGetSymbolAddress((void**)&Xh, g_Xh);      cudaGetSymbolAddress((void**)&Xl, g_Xl);
    cudaGetSymbolAddress((void**)&Wkth, g_Wkt_h); cudaGetSymbolAddress((void**)&Wktl, g_Wkt_l);
    cudaGetSymbolAddress((void**)&Wvth, g_Wvt_h); cudaGetSymbolAddress((void**)&Wvtl, g_Wvt_l);
    cudaGetSymbolAddress((void**)&Wpth, g_Wpt_h); cudaGetSymbolAddress((void**)&Wptl, g_Wpt_l);
    cudaGetSymbolAddress((void**)&Wgth, g_Wgt_h); cudaGetSymbolAddress((void**)&Wgtl, g_Wgt_l);
    cudaGetSymbolAddress((void**)&kb, g_k);       cudaGetSymbolAddress((void**)&vb, g_v);
    cudaGetSymbolAddress((void**)&ah, g_ah);      cudaGetSymbolAddress((void**)&al, g_al);
    cudaGetSymbolAddress((void**)&Pb, g_P);
    cudaGetSymbolAddress((void**)&Pth, g_Pth);    cudaGetSymbolAddress((void**)&Ptl, g_Ptl);
    cudaGetSymbolAddress((void**)&Gh, g_Gh);      cudaGetSymbolAddress((void**)&Gl, g_Gl);

    cudaFuncSetAttribute(mm_tc<0>, cudaFuncAttributeMaxDynamicSharedMemorySize, MM_SMEM);
    cudaFuncSetAttribute(mm_tc<2>, cudaFuncAttributeMaxDynamicSharedMemorySize, MM_SMEM);
    cudaFuncSetAttribute(attn2, cudaFuncAttributeMaxDynamicSharedMemorySize, ATTN_SMEM);

    // 1) X -> bf16 hi/lo
    fsplit<<<32768, 256>>>(x, Xh, Xl, (size_t)16384 * 2048);
    // 2) weight transposes+splits: W[K,N] -> Wt[N,K]
    {
        dim3 blk(32, 8);
        tsplit<<<dim3(64, 64, 1), blk>>>(Wk, Wkth, Wktl, 2048, 2048, 0, 0);
        tsplit<<<dim3(64, 64, 1), blk>>>(Wv, Wvth, Wvtl, 2048, 2048, 0, 0);
        tsplit<<<dim3(64, 64, 1), blk>>>(Wp, Wpth, Wptl, 2048, 2048, 0, 0);
        tsplit<<<dim3(32, 64, 1), blk>>>(Wg, Wgth, Wgtl, 2048, 1024, 0, 0);
    }
    // 3) k/v = x[:, :64] @ Wk/Wv  (M=64 per batch)
    mm_tc<0><<<dim3(16, 1, BATCH), 256, MM_SMEM>>>(
        Xh, Xl, Wkth, Wktl, kb, nullptr, nullptr,
        64, 2048, 2048, 2048, 2048,
        (long long)SEQ * CM, 0LL, (long long)NLAT * CM, 1);
    mm_tc<0><<<dim3(16, 1, BATCH), 256, MM_SMEM>>>(
        Xh, Xl, Wvth, Wvtl, vb, nullptr, nullptr,
        64, 2048, 2048, 2048, 2048,
        (long long)SEQ * CM, 0LL, (long long)NLAT * CM, 1);
    // 4) RoPE on k
    rope_kernel<<<(BATCH * NLAT * NHEAD * 64 + 255) / 256, 256>>>(kb);
    // 5) attention -> ah/al bf16 hi/lo
    attn2<<<BATCH * NHEAD, 256, ATTN_SMEM>>>(lq, kb, vb, ah, al);
    // 6) P[b,h] = attn[b,h] @ Wp[h*128:(h+1)*128, :]   (z = b*16+h, M=64, K=128)
    mm_tc<0><<<dim3(16, 1, BATCH * NHEAD), 256, MM_SMEM>>>(
        ah, al, Wpth, Wptl, Pb, nullptr, nullptr,
        64, 128, 128, 2048, 2048,
        (long long)NLAT * HDIM, 128LL, (long long)NLAT * CM, NHEAD);
    // 7) P[b] [1024,2048] -> Pt[b] [2048,1024] hi/lo
    {
        dim3 blk(32, 8);
        tsplit<<<dim3(64, 32, BATCH), blk>>>(Pb, Pth, Ptl, 1024, 2048,
                                             (long long)HL * CM, (long long)CM * HL);
    }
    // 8) gates = softmax64(x @ Wg * SCALE) -> bf16 hi/lo (fused epilogue)
    mm_tc<2><<<dim3(8, 128, 1), 256, MM_SMEM>>>(
        Xh, Xl, Wgth, Wgtl, nullptr, Gh, Gl,
        16384, 2048, 2048, 2048, 1024,
        0LL, 0LL, 0LL, 1);
    // 9) out[b] = gates[b] [4096,1024] @ Pt[b]^T -> [4096,2048]
    mm_tc<0><<<dim3(16, 32, BATCH), 256, MM_SMEM>>>(
        Gh, Gl, Pth, Ptl, out, nullptr, nullptr,
        4096, 1024, 1024, 1024, 2048,
        (long long)SEQ * HL, (long long)CM * HL, (long long)SEQ * CM, 0);
}

// round 11
// speedup vs baseline: 5.5069x; 1.4713x over previous
#include <cuda_runtime.h>
#include <cuda_bf16.h>
#include <cuda_fp16.h>
#include <cstdint>
#include <math.h>

#define BATCH 4
#define SEQ 4096
#define CM 2048
#define NHEAD 16
#define HDIM 128
#define NLAT 64
#define HL 1024
#define SCALE_F 0.08838834764831845f

typedef __nv_bfloat16 bf16;

// ------------------- device scratch (no allocations allowed) -------------------
__device__ __half g_Xf[(size_t)16384 * 2048];          // X fp16 (for gates GEMM)
__device__ bf16 g_X64h[(size_t)BATCH * 64 * 2048];     // X rows t<64, bf16 hi
__device__ bf16 g_X64l[(size_t)BATCH * 64 * 2048];     // X rows t<64, bf16 lo
__device__ bf16 g_Wkt_h[(size_t)2048 * 2048];
__device__ bf16 g_Wkt_l[(size_t)2048 * 2048];
__device__ bf16 g_Wvt_h[(size_t)2048 * 2048];
__device__ bf16 g_Wvt_l[(size_t)2048 * 2048];
__device__ bf16 g_Wpt_h[(size_t)2048 * 2048];
__device__ bf16 g_Wpt_l[(size_t)2048 * 2048];
__device__ __half g_Wgt_f[(size_t)1024 * 2048];        // Wg^T fp16 single
__device__ float g_k[BATCH * NLAT * CM];
__device__ float g_v[BATCH * NLAT * CM];
__device__ bf16 g_ah[BATCH * NHEAD * NLAT * HDIM];
__device__ bf16 g_al[BATCH * NHEAD * NLAT * HDIM];
__device__ float g_P[(size_t)BATCH * HL * CM];
__device__ __half g_Ptf[(size_t)BATCH * CM * HL];      // P^T fp16 single
__device__ __half g_Gh[(size_t)16384 * 1024];          // gates fp16 hi
__device__ __half g_Gl[(size_t)16384 * 1024];          // gates fp16 lo

// ------------------- helpers (baseline PTX only) -------------------
__device__ __forceinline__ uint32_t smem_u32(const void* p) {
    uint32_t a;
    asm("{ .reg .u64 t; cvta.to.shared.u64 t, %1; cvt.u32.u64 %0, t; }" : "=r"(a) : "l"(p));
    return a;
}
__device__ __forceinline__ void cpa16(uint32_t sdst, const void* gsrc) {
    asm volatile("cp.async.cg.shared.global [%0], [%1], 16;" :: "r"(sdst), "l"(gsrc));
}
#define CP_COMMIT() asm volatile("cp.async.commit_group;" ::: "memory")
#define CP_WAIT2()  asm volatile("cp.async.wait_group 2;" ::: "memory")
#define CP_WAIT1()  asm volatile("cp.async.wait_group 1;" ::: "memory")
#define CP_WAIT0()  asm volatile("cp.async.wait_group 0;" ::: "memory")

__device__ __forceinline__ void ldsm4(uint32_t* r, uint32_t addr) {
    asm volatile("ldmatrix.sync.aligned.m8n8.x4.shared.b16 {%0,%1,%2,%3}, [%4];"
                 : "=r"(r[0]), "=r"(r[1]), "=r"(r[2]), "=r"(r[3]) : "r"(addr));
}
__device__ __forceinline__ void mma_bf16(float* c, const uint32_t* a, const uint32_t* b) {
    asm volatile(
        "mma.sync.aligned.m16n8k16.row.col.f32.bf16.bf16.f32 "
        "{%0,%1,%2,%3}, {%4,%5,%6,%7}, {%8,%9}, {%0,%1,%2,%3};"
        : "+f"(c[0]), "+f"(c[1]), "+f"(c[2]), "+f"(c[3])
        : "r"(a[0]), "r"(a[1]), "r"(a[2]), "r"(a[3]), "r"(b[0]), "r"(b[1]));
}
__device__ __forceinline__ void mma_f16(float* c, const uint32_t* a, const uint32_t* b) {
    asm volatile(
        "mma.sync.aligned.m16n8k16.row.col.f32.f16.f16.f32 "
        "{%0,%1,%2,%3}, {%4,%5,%6,%7}, {%8,%9}, {%0,%1,%2,%3};"
        : "+f"(c[0]), "+f"(c[1]), "+f"(c[2]), "+f"(c[3])
        : "r"(a[0]), "r"(a[1]), "r"(a[2]), "r"(a[3]), "r"(b[0]), "r"(b[1]));
}
__device__ __forceinline__ uint32_t swz(uint32_t off) { return off ^ ((off >> 3) & 0x70); }

// =================== configurable split warp-MMA GEMM ===================
// C[M,N] = A[M,K] @ B[N,K]^T with A as APL planes, B as BPL planes (2-byte elems).
// Products: A0*B0 (+ A1*B0 if APL==2) (+ A0*B1 if BPL==2).
// MODE 0: fp32 C (row-guarded).  MODE 2: fused 64-group softmax(*SCALE) -> Ch/Cl fp16.
// Tile 128x128x64; 256 thr = 8 warps (2M x 4N); warp tile 64x32; 3-stage cp.async.
template <int APL, int BPL, int MODE, int FP16>
__global__ __launch_bounds__(256, 1)
void mm_tc(const uint16_t* __restrict__ A0, const uint16_t* __restrict__ A1,
           const uint16_t* __restrict__ B0, const uint16_t* __restrict__ B1,
           float* __restrict__ C, __half* __restrict__ Ch, __half* __restrict__ Cl,
           int M, int K, int lda, int ldb, int ldc,
           long long aStride, long long bStride, long long cStride, int bModulo)
{
    constexpr uint32_t SZ = (APL + BPL) * 16384u;
    extern __shared__ char smem[];
    const uint32_t sb = smem_u32(smem);

    const int tid = threadIdx.x;
    const int wid = tid >> 5, lane = tid & 31;
    const int warpM = wid >> 2;
    const int warpN = wid & 3;
    const int z = blockIdx.z;
    const int rowBase = blockIdx.y * 128;
    const int colBase = blockIdx.x * 128;

    A0 += (long long)z * aStride;
    if (APL == 2) A1 += (long long)z * aStride;
    const long long bo = (long long)(bModulo > 0 ? (z % bModulo) : z) * bStride;
    B0 += bo;
    if (BPL == 2) B1 += bo;
    const long long co = (long long)z * cStride;

    int sr[4], su[4];
    #pragma unroll
    for (int i = 0; i < 4; i++) {
        const int q = (i << 8) + tid;
        sr[i] = q >> 3;
        su[i] = q & 7;
    }

    float acc[4][4][4];
    #pragma unroll
    for (int mi = 0; mi < 4; mi++)
        #pragma unroll
        for (int ni = 0; ni < 4; ni++)
            #pragma unroll
            for (int e = 0; e < 4; e++) acc[mi][ni][e] = 0.f;

    const int nC = K >> 6;

    auto issue = [&](int c) {
        const int k0 = c << 6;
        const uint32_t st = sb + (uint32_t)(c % 3) * SZ;
        #pragma unroll
        for (int i = 0; i < 4; i++) {
            const int r = sr[i];
            const uint32_t so = swz((uint32_t)(r * 128 + su[i] * 16));
            const int kk = k0 + su[i] * 8;
            int ga = rowBase + r; if (ga >= M) ga = M - 1;   // clamp: finite garbage, never stored
            const int gb = colBase + r;
            cpa16(st + so, A0 + (size_t)ga * lda + kk);
            if (APL == 2) cpa16(st + 16384 + so, A1 + (size_t)ga * lda + kk);
            cpa16(st + APL * 16384 + so, B0 + (size_t)gb * ldb + kk);
            if (BPL == 2) cpa16(st + APL * 16384 + 16384 + so, B1 + (size_t)gb * ldb + kk);
        }
        CP_COMMIT();
    };

    issue(0);
    if (nC > 1) issue(1);
    for (int c = 0; c < nC; c++) {
        if (c + 2 < nC) { issue(c + 2); CP_WAIT2(); }
        else if (c + 1 < nC) CP_WAIT1();
        else CP_WAIT0();
        __syncthreads();

        const uint32_t st = sb + (uint32_t)(c % 3) * SZ;
        const uint32_t sA0 = st;
        const uint32_t sA1 = st + 16384;
        const uint32_t sB0 = st + APL * 16384;
        const uint32_t sB1 = sB0 + 16384;

        const int aRow16 = lane & 15;
        const int aUhalf = lane >> 4;
        const int bRow   = ((lane >> 4) & 1) * 8 + (lane & 7);
        const int bUhalf = (lane >> 3) & 1;

        #pragma unroll
        for (int ks = 0; ks < 4; ks++) {
            uint32_t a0[4][4], a1[4][4];
            #pragma unroll
            for (int mi = 0; mi < 4; mi++) {
                const int row = warpM * 64 + mi * 16 + aRow16;
                const uint32_t off = swz((uint32_t)(row * 128 + (ks * 2 + aUhalf) * 16));
                ldsm4(a0[mi], sA0 + off);
                if (APL == 2) ldsm4(a1[mi], sA1 + off);
            }
            uint32_t b0[4][2], b1[4][2];
            #pragma unroll
            for (int nb = 0; nb < 2; nb++) {
                const int row = warpN * 32 + nb * 16 + bRow;
                const uint32_t off = swz((uint32_t)(row * 128 + (ks * 2 + bUhalf) * 16));
                uint32_t t[4];
                ldsm4(t, sB0 + off);
                b0[nb * 2][0] = t[0]; b0[nb * 2][1] = t[1];
                b0[nb * 2 + 1][0] = t[2]; b0[nb * 2 + 1][1] = t[3];
                if (BPL == 2) {
                    ldsm4(t, sB1 + off);
                    b1[nb * 2][0] = t[0]; b1[nb * 2][1] = t[1];
                    b1[nb * 2 + 1][0] = t[2]; b1[nb * 2 + 1][1] = t[3];
                }
            }
            #pragma unroll
            for (int mi = 0; mi < 4; mi++)
                #pragma unroll
                for (int ni = 0; ni < 4; ni++) {
                    if (FP16) {
                        mma_f16(acc[mi][ni], a0[mi], b0[ni]);
                        if (APL == 2) mma_f16(acc[mi][ni], a1[mi], b0[ni]);
                        if (BPL == 2) mma_f16(acc[mi][ni], a0[mi], b1[ni]);
                    } else {
                        mma_bf16(acc[mi][ni], a0[mi], b0[ni]);
                        if (APL == 2) mma_bf16(acc[mi][ni], a1[mi], b0[ni]);
                        if (BPL == 2) mma_bf16(acc[mi][ni], a0[mi], b1[ni]);
                    }
                }
        }
        __syncthreads();
    }

    const int lr = lane >> 2;
    const int lc = (lane & 3) * 2;

    if (MODE == 0) {
        #pragma unroll
        for (int mi = 0; mi < 4; mi++)
            #pragma unroll
            for (int ni = 0; ni < 4; ni++) {
                const int r0 = rowBase + warpM * 64 + mi * 16 + lr;
                const int cc = colBase + warpN * 32 + ni * 8 + lc;
                if (r0 < M)
                    *reinterpret_cast<float2*>(&C[co + (size_t)r0 * ldc + cc]) =
                        make_float2(acc[mi][ni][0], acc[mi][ni][1]);
                if (r0 + 8 < M)
                    *reinterpret_cast<float2*>(&C[co + (size_t)(r0 + 8) * ldc + cc]) =
                        make_float2(acc[mi][ni][2], acc[mi][ni][3]);
            }
    } else {
        float* es = reinterpret_cast<float*>(smem);   // 128 x 129 fp32 (aliases stages; synced)
        #pragma unroll
        for (int mi = 0; mi < 4; mi++)
            #pragma unroll
            for (int ni = 0; ni < 4; ni++) {
                const int r0 = warpM * 64 + mi * 16 + lr;
                const int cc = warpN * 32 + ni * 8 + lc;
                es[r0 * 129 + cc]           = acc[mi][ni][0];
                es[r0 * 129 + cc + 1]       = acc[mi][ni][1];
                es[(r0 + 8) * 129 + cc]     = acc[mi][ni][2];
                es[(r0 + 8) * 129 + cc + 1] = acc[mi][ni][3];
            }
        __syncthreads();
        {   // 64-group softmax: 256 threads = 128 rows x 2 groups
            const int r = tid & 127, g = tid >> 7;
            float* p = es + r * 129 + g * 64;
            float m = -1e30f;
            #pragma unroll 4
            for (int i = 0; i < 64; i++) m = fmaxf(m, p[i] * SCALE_F);
            float s = 0.f;
            #pragma unroll 4
            for (int i = 0; i < 64; i++) { float e = __expf(p[i] * SCALE_F - m); p[i] = e; s += e; }
            const float inv = 1.0f / s;
            #pragma unroll 4
            for (int i = 0; i < 64; i++) p[i] *= inv;
        }
        __syncthreads();
        for (int idx = tid; idx < 16384; idx += 256) {
            const int r = idx >> 7, cc = idx & 127;
            const float v = es[r * 129 + cc];
            const __half h = __float2half(v);
            const __half l = __float2half(v - __half2float(h));
            const size_t o = (size_t)(rowBase + r) * ldc + colBase + cc;
            Ch[o] = h; Cl[o] = l;
        }
    }
}

// =================== X -> fp16 single ===================
__global__ void fsplit_f16(const float* __restrict__ src, __half* __restrict__ dst, size_t n)
{
    size_t i = ((size_t)blockIdx.x * blockDim.x + threadIdx.x) * 4;
    if (i >= n) return;
    float4 v = *reinterpret_cast<const float4*>(src + i);
    __half2 p0 = __floats2half2_rn(v.x, v.y);
    __half2 p1 = __floats2half2_rn(v.z, v.w);
    uint2 o;
    o.x = *reinterpret_cast<uint32_t*>(&p0);
    o.y = *reinterpret_cast<uint32_t*>(&p1);
    *reinterpret_cast<uint2*>(dst + i) = o;
}

// =================== X rows t<64 per batch -> bf16 hi/lo compact [B*64, 2048] ===================
__global__ void xsplit64(const float* __restrict__ x, bf16* __restrict__ h, bf16* __restrict__ l)
{
    int idx = blockIdx.x * blockDim.x + threadIdx.x;   // 131072 float4's
    if (idx >= BATCH * 64 * 2048 / 4) return;
    const int e = idx * 4;
    const int c = e & 2047;
    const int row = e >> 11;           // b*64 + t
    const int b = row >> 6, t = row & 63;
    float4 v = *reinterpret_cast<const float4*>(&x[((size_t)(b * SEQ + t)) * CM + c]);
    const size_t o = (size_t)row * CM + c;
    bf16 h0 = __float2bfloat16(v.x), h1 = __float2bfloat16(v.y);
    bf16 h2 = __float2bfloat16(v.z), h3 = __float2bfloat16(v.w);
    h[o] = h0; h[o + 1] = h1; h[o + 2] = h2; h[o + 3] = h3;
    l[o]     = __float2bfloat16(v.x - __bfloat162float(h0));
    l[o + 1] = __float2bfloat16(v.y - __bfloat162float(h1));
    l[o + 2] = __float2bfloat16(v.z - __bfloat162float(h2));
    l[o + 3] = __float2bfloat16(v.w - __bfloat162float(h3));
}

// =================== transpose + bf16 hi/lo split ===================
__global__ void tsplit(const float* __restrict__ src, bf16* __restrict__ dh,
                       bf16* __restrict__ dl, int R, int C,
                       long long sStride, long long dStride)
{
    __shared__ float t[32][33];
    const int z = blockIdx.z;
    src += (long long)z * sStride;
    dh += (long long)z * dStride;
    dl += (long long)z * dStride;
    const int c0 = blockIdx.x * 32, r0 = blockIdx.y * 32;
    const int x = threadIdx.x, y = threadIdx.y;
    #pragma unroll
    for (int j = 0; j < 32; j += 8)
        t[y + j][x] = src[(size_t)(r0 + y + j) * C + c0 + x];
    __syncthreads();
    #pragma unroll
    for (int j = 0; j < 32; j += 8) {
        const float v = t[x][y + j];
        const bf16 h = __float2bfloat16(v);
        const bf16 l = __float2bfloat16(v - __bfloat162float(h));
        const size_t o = (size_t)(c0 + y + j) * R + r0 + x;
        dh[o] = h; dl[o] = l;
    }
}

// =================== transpose + fp16 single ===================
__global__ void tsplit_f16(const float* __restrict__ src, __half* __restrict__ d,
                           int R, int C, long long sStride, long long dStride)
{
    __shared__ float t[32][33];
    const int z = blockIdx.z;
    src += (long long)z * sStride;
    d += (long long)z * dStride;
    const int c0 = blockIdx.x * 32, r0 = blockIdx.y * 32;
    const int x = threadIdx.x, y = threadIdx.y;
    #pragma unroll
    for (int j = 0; j < 32; j += 8)
        t[y + j][x] = src[(size_t)(r0 + y + j) * C + c0 + x];
    __syncthreads();
    #pragma unroll
    for (int j = 0; j < 32; j += 8)
        d[(size_t)(c0 + y + j) * R + r0 + x] = __float2half(t[x][y + j]);
}

// =================== RoPE on g_k : [B, 64, H, D] fp32 ===================
__global__ void rope_kernel(float* __restrict__ k)
{
    int idx = blockIdx.x * blockDim.x + threadIdx.x;
    if (idx >= BATCH * NLAT * NHEAD * (HDIM / 2)) return;
    const int i = idx & 63;
    const int h = (idx >> 6) & 15;
    const int t = (idx >> 10) & 63;
    const int b = idx >> 16;
    const float inv_freq = expf(-(2.0f * i / 128.0f) * 9.210340371976184f);
    float s, c;
    __sincosf((float)t * inv_freq, &s, &c);
    const size_t base = ((((size_t)b * NLAT + t) * NHEAD + h) * HDIM) + 2 * i;
    const float x0 = k[base], x1 = k[base + 1];
    k[base]     = x0 * c - x1 * s;
    k[base + 1] = x0 * s + x1 * c;
}

// =================== small causal attention, outputs bf16 hi/lo ===================
#define ATTN_SMEM ((8192 + 64*129 + 64*129 + 64*65) * 4)
__global__ __launch_bounds__(256, 1) void attn2(
    const float* __restrict__ lq, const float* __restrict__ k, const float* __restrict__ v,
    bf16* __restrict__ ah, bf16* __restrict__ al)
{
    extern __shared__ float s[];
    float* sQ = s;
    float* sK = s + 8192;
    float* sV = sK + 64 * 129;
    float* sS = sV + 64 * 129;
    const int b = blockIdx.x >> 4, h = blockIdx.x & 15;
    const int tid = threadIdx.x;

    for (int i = tid; i < 8192; i += 256) {
        const int t = i >> 7, d = i & 127;
        sQ[i] = lq[(t * 16 + h) * 128 + d];
        const size_t gi = (((size_t)(b * 64 + t)) * 16 + h) * 128 + d;
        sK[t * 129 + d] = k[gi];
        sV[t * 129 + d] = v[gi];
    }
    __syncthreads();

    for (int i = tid; i < 4096; i += 256) {
        const int l = i >> 6, t = i & 63;
        float sc = -1e9f;
        if (t <= l) {
            const float* qp = sQ + l * 128;
            const float* kp = sK + t * 129;
            float a0 = 0.f, a1 = 0.f, a2 = 0.f, a3 = 0.f;
            #pragma unroll
            for (int d = 0; d < 128; d += 4) {
                a0 += qp[d] * kp[d];         a1 += qp[d + 1] * kp[d + 1];
                a2 += qp[d + 2] * kp[d + 2]; a3 += qp[d + 3] * kp[d + 3];
            }
            sc = (a0 + a1 + a2 + a3) * SCALE_F;
        }
        sS[l * 65 + t] = sc;
    }
    __syncthreads();

    if (tid < 64) {
        float* p = sS + tid * 65;
        float m = -1e30f;
        for (int t = 0; t < 64; t++) m = fmaxf(m, p[t]);
        float sum = 0.f;
        for (int t = 0; t < 64; t++) { float e = __expf(p[t] - m); p[t] = e; sum += e; }
        const float inv = 1.0f / sum;
        for (int t = 0; t < 64; t++) p[t] *= inv;
    }
    __syncthreads();

    for (int i = tid; i < 8192; i += 256) {
        const int l = i >> 7, d = i & 127;
        const float* w = sS + l * 65;
        float a0 = 0.f, a1 = 0.f, a2 = 0.f, a3 = 0.f;
        #pragma unroll
        for (int t = 0; t < 64; t += 4) {
            a0 += w[t] * sV[t * 129 + d];
            a1 += w[t + 1] * sV[(t + 1) * 129 + d];
            a2 += w[t + 2] * sV[(t + 2) * 129 + d];
            a3 += w[t + 3] * sV[(t + 3) * 129 + d];
        }
        const float acc = a0 + a1 + a2 + a3;
        const size_t o = ((size_t)(b * 16 + h) * 64 + l) * 128 + d;
        const bf16 hh = __float2bfloat16(acc);
        ah[o] = hh;
        al[o] = __float2bfloat16(acc - __bfloat162float(hh));
    }
}

// =================== launch ===================
extern "C" void kernel_launch(void* const* d_in, const int* in_sizes, int n_in,
                              void* d_out, int out_size)
{
    const float* x  = (const float*)d_in[0];
    const float* lq = (const float*)d_in[1];
    const float* Wk = (const float*)d_in[2];
    const float* Wv = (const float*)d_in[3];
    const float* Wg = (const float*)d_in[4];
    const float* Wp = (const float*)d_in[5];
    float* out = (float*)d_out;

    __half *Xf, *Wgtf, *Ptf, *Gh, *Gl;
    bf16 *X64h, *X64l, *Wkth, *Wktl, *Wvth, *Wvtl, *Wpth, *Wptl, *ah, *al;
    float *kb, *vb, *Pb;
    cudaGetSymbolAddress((void**)&Xf, g_Xf);
    cudaGetSymbolAddress((void**)&X64h, g_X64h);  cudaGetSymbolAddress((void**)&X64l, g_X64l);
    cudaGetSymbolAddress((void**)&Wkth, g_Wkt_h); cudaGetSymbolAddress((void**)&Wktl, g_Wkt_l);
    cudaGetSymbolAddress((void**)&Wvth, g_Wvt_h); cudaGetSymbolAddress((void**)&Wvtl, g_Wvt_l);
    cudaGetSymbolAddress((void**)&Wpth, g_Wpt_h); cudaGetSymbolAddress((void**)&Wptl, g_Wpt_l);
    cudaGetSymbolAddress((void**)&Wgtf, g_Wgt_f);
    cudaGetSymbolAddress((void**)&kb, g_k);       cudaGetSymbolAddress((void**)&vb, g_v);
    cudaGetSymbolAddress((void**)&ah, g_ah);      cudaGetSymbolAddress((void**)&al, g_al);
    cudaGetSymbolAddress((void**)&Pb, g_P);       cudaGetSymbolAddress((void**)&Ptf, g_Ptf);
    cudaGetSymbolAddress((void**)&Gh, g_Gh);      cudaGetSymbolAddress((void**)&Gl, g_Gl);

    // smem sizes: (APL+BPL)*16KB * 3 stages
    const int SM22 = 3 * 4 * 16384;   // 192KB  (bf16x3 kv/P)
    const int SM11 = 3 * 2 * 16384;   //  96KB  (gates fp16 1-pass)
    const int SM21 = 3 * 3 * 16384;   // 144KB  (out fp16 2-pass)
    cudaFuncSetAttribute(mm_tc<2,2,0,0>, cudaFuncAttributeMaxDynamicSharedMemorySize, SM22);
    cudaFuncSetAttribute(mm_tc<1,1,2,1>, cudaFuncAttributeMaxDynamicSharedMemorySize, SM11);
    cudaFuncSetAttribute(mm_tc<2,1,0,1>, cudaFuncAttributeMaxDynamicSharedMemorySize, SM21);
    cudaFuncSetAttribute(attn2, cudaFuncAttributeMaxDynamicSharedMemorySize, ATTN_SMEM);

    // 1) X -> fp16 (gates GEMM A); X rows t<64 -> bf16 hi/lo (kv GEMM A)
    fsplit_f16<<<32768, 256>>>(x, Xf, (size_t)16384 * 2048);
    xsplit64<<<512, 256>>>(x, X64h, X64l);
    // 2) weight transposes
    {
        dim3 blk(32, 8);
        tsplit<<<dim3(64, 64, 1), blk>>>(Wk, Wkth, Wktl, 2048, 2048, 0, 0);
        tsplit<<<dim3(64, 64, 1), blk>>>(Wv, Wvth, Wvtl, 2048, 2048, 0, 0);
        tsplit<<<dim3(64, 64, 1), blk>>>(Wp, Wpth, Wptl, 2048, 2048, 0, 0);
        tsplit_f16<<<dim3(32, 64, 1), blk>>>(Wg, Wgtf, 2048, 1024, 0, 0);
    }
    // 3) k/v = x[:, :64] @ Wk/Wv  (bf16x3 exact; M=64 per batch)
    mm_tc<2,2,0,0><<<dim3(16, 1, BATCH), 256, SM22>>>(
        (const uint16_t*)X64h, (const uint16_t*)X64l,
        (const uint16_t*)Wkth, (const uint16_t*)Wktl,
        kb, nullptr, nullptr,
        64, 2048, 2048, 2048, 2048,
        (long long)64 * CM, 0LL, (long long)NLAT * CM, 1);
    mm_tc<2,2,0,0><<<dim3(16, 1, BATCH), 256, SM22>>>(
        (const uint16_t*)X64h, (const uint16_t*)X64l,
        (const uint16_t*)Wvth, (const uint16_t*)Wvtl,
        vb, nullptr, nullptr,
        64, 2048, 2048, 2048, 2048,
        (long long)64 * CM, 0LL, (long long)NLAT * CM, 1);
    // 4) RoPE on k
    rope_kernel<<<(BATCH * NLAT * NHEAD * 64 + 255) / 256, 256>>>(kb);
    // 5) attention -> ah/al bf16 hi/lo
    attn2<<<BATCH * NHEAD, 256, ATTN_SMEM>>>(lq, kb, vb, ah, al);
    // 6) P[b,h] = attn[b,h] @ Wp[h*128:(h+1)*128, :]   (bf16x3; z = b*16+h, M=64, K=128)
    mm_tc<2,2,0,0><<<dim3(16, 1, BATCH * NHEAD), 256, SM22>>>(
        (const uint16_t*)ah, (const uint16_t*)al,
        (const uint16_t*)Wpth, (const uint16_t*)Wptl,
        Pb, nullptr, nullptr,
        64, 128, 128, 2048, 2048,
        (long long)NLAT * HDIM, 128LL, (long long)NLAT * CM, NHEAD);
    // 7) P[b] [1024,2048] -> Pt[b] [2048,1024] fp16
    {
        dim3 blk(32, 8);
        tsplit_f16<<<dim3(64, 32, BATCH), blk>>>(Pb, Ptf, 1024, 2048,
                                                 (long long)HL * CM, (long long)CM * HL);
    }
    // 8) gates = softmax64(x @ Wg * SCALE) -> fp16 hi/lo (fp16 single-pass + fused epilogue)
    mm_tc<1,1,2,1><<<dim3(8, 128, 1), 256, SM11>>>(
        (const uint16_t*)Xf, nullptr,
        (const uint16_t*)Wgtf, nullptr,
        nullptr, Gh, Gl,
        16384, 2048, 2048, 2048, 1024,
        0LL, 0LL, 0LL, 1);
    // 9) out[b] = gates[b] @ Pt[b]^T  (fp16, gates split 2-pass, P single)
    mm_tc<2,1,0,1><<<dim3(16, 32, BATCH), 256, SM21>>>(
        (const uint16_t*)Gh, (const uint16_t*)Gl,
        (const uint16_t*)Ptf, nullptr,
        out, nullptr, nullptr,
        4096, 1024, 1024, 1024, 2048,
        (long long)SEQ * HL, (long long)CM * HL, (long long)SEQ * CM, 0);
}

// round 12
// speedup vs baseline: 6.5254x; 1.1850x over previous
#include <cuda_runtime.h>
#include <cuda_bf16.h>
#include <cuda_fp16.h>
#include <cstdint>
#include <math.h>

#define BATCH 4
#define SEQ 4096
#define CM 2048
#define NHEAD 16
#define HDIM 128
#define NLAT 64
#define HL 1024
#define SCALE_F 0.08838834764831845f

typedef __nv_bfloat16 bf16;

// ------------------- device scratch (no allocations allowed) -------------------
__device__ __half g_Xf[(size_t)16384 * 2048];          // X fp16 (for gates GEMM)
__device__ bf16 g_X64h[(size_t)BATCH * 64 * 2048];     // X rows t<64, bf16 hi
__device__ bf16 g_X64l[(size_t)BATCH * 64 * 2048];     // X rows t<64, bf16 lo
__device__ bf16 g_Wkt_h[(size_t)2048 * 2048];
__device__ bf16 g_Wkt_l[(size_t)2048 * 2048];
__device__ bf16 g_Wvt_h[(size_t)2048 * 2048];
__device__ bf16 g_Wvt_l[(size_t)2048 * 2048];
__device__ bf16 g_Wpt_h[(size_t)2048 * 2048];
__device__ bf16 g_Wpt_l[(size_t)2048 * 2048];
__device__ __half g_Wgt_f[(size_t)1024 * 2048];        // Wg^T fp16 single
__device__ float g_k[BATCH * NLAT * CM];
__device__ float g_v[BATCH * NLAT * CM];
__device__ bf16 g_ah[BATCH * NHEAD * NLAT * HDIM];
__device__ bf16 g_al[BATCH * NHEAD * NLAT * HDIM];
__device__ float g_P[(size_t)BATCH * HL * CM];
__device__ __half g_Ptf[(size_t)BATCH * CM * HL];      // P^T fp16 single
__device__ __half g_Gh[(size_t)16384 * 1024];          // gates fp16

// ------------------- helpers (baseline PTX only) -------------------
__device__ __forceinline__ uint32_t smem_u32(const void* p) {
    uint32_t a;
    asm("{ .reg .u64 t; cvta.to.shared.u64 t, %1; cvt.u32.u64 %0, t; }" : "=r"(a) : "l"(p));
    return a;
}
__device__ __forceinline__ void cpa16(uint32_t sdst, const void* gsrc) {
    asm volatile("cp.async.cg.shared.global [%0], [%1], 16;" :: "r"(sdst), "l"(gsrc));
}
#define CP_COMMIT() asm volatile("cp.async.commit_group;" ::: "memory")
#define CP_WAIT2()  asm volatile("cp.async.wait_group 2;" ::: "memory")
#define CP_WAIT1()  asm volatile("cp.async.wait_group 1;" ::: "memory")
#define CP_WAIT0()  asm volatile("cp.async.wait_group 0;" ::: "memory")

__device__ __forceinline__ void ldsm4(uint32_t* r, uint32_t addr) {
    asm volatile("ldmatrix.sync.aligned.m8n8.x4.shared.b16 {%0,%1,%2,%3}, [%4];"
                 : "=r"(r[0]), "=r"(r[1]), "=r"(r[2]), "=r"(r[3]) : "r"(addr));
}
__device__ __forceinline__ void mma_bf16(float* c, const uint32_t* a, const uint32_t* b) {
    asm volatile(
        "mma.sync.aligned.m16n8k16.row.col.f32.bf16.bf16.f32 "
        "{%0,%1,%2,%3}, {%4,%5,%6,%7}, {%8,%9}, {%0,%1,%2,%3};"
        : "+f"(c[0]), "+f"(c[1]), "+f"(c[2]), "+f"(c[3])
        : "r"(a[0]), "r"(a[1]), "r"(a[2]), "r"(a[3]), "r"(b[0]), "r"(b[1]));
}
__device__ __forceinline__ void mma_f16(float* c, const uint32_t* a, const uint32_t* b) {
    asm volatile(
        "mma.sync.aligned.m16n8k16.row.col.f32.f16.f16.f32 "
        "{%0,%1,%2,%3}, {%4,%5,%6,%7}, {%8,%9}, {%0,%1,%2,%3};"
        : "+f"(c[0]), "+f"(c[1]), "+f"(c[2]), "+f"(c[3])
        : "r"(a[0]), "r"(a[1]), "r"(a[2]), "r"(a[3]), "r"(b[0]), "r"(b[1]));
}
__device__ __forceinline__ uint32_t swz(uint32_t off) { return off ^ ((off >> 3) & 0x70); }

// =================== configurable split warp-MMA GEMM ===================
// C[M,N] = A[M,K] @ B[N,K]^T with A as APL planes, B as BPL planes (2-byte elems).
// Products: A0*B0 (+ A1*B0 if APL==2) (+ A0*B1 if BPL==2).
// MODE 0: fp32 C (row-guarded).  MODE 2: fused 64-group softmax(*SCALE) -> Ch fp16.
// Tile 128x128x64; 256 thr = 8 warps (2M x 4N); warp tile 64x32; 3-stage cp.async.
template <int APL, int BPL, int MODE, int FP16>
__global__ __launch_bounds__(256, 1)
void mm_tc(const uint16_t* __restrict__ A0, const uint16_t* __restrict__ A1,
           const uint16_t* __restrict__ B0, const uint16_t* __restrict__ B1,
           float* __restrict__ C, __half* __restrict__ Ch,
           int M, int K, int lda, int ldb, int ldc,
           long long aStride, long long bStride, long long cStride, int bModulo)
{
    constexpr uint32_t SZ = (APL + BPL) * 16384u;
    extern __shared__ char smem[];
    const uint32_t sb = smem_u32(smem);

    const int tid = threadIdx.x;
    const int wid = tid >> 5, lane = tid & 31;
    const int warpM = wid >> 2;
    const int warpN = wid & 3;
    const int z = blockIdx.z;
    const int rowBase = blockIdx.y * 128;
    const int colBase = blockIdx.x * 128;

    A0 += (long long)z * aStride;
    if (APL == 2) A1 += (long long)z * aStride;
    const long long bo = (long long)(bModulo > 0 ? (z % bModulo) : z) * bStride;
    B0 += bo;
    if (BPL == 2) B1 += bo;
    const long long co = (long long)z * cStride;

    int sr[4], su[4];
    #pragma unroll
    for (int i = 0; i < 4; i++) {
        const int q = (i << 8) + tid;
        sr[i] = q >> 3;
        su[i] = q & 7;
    }

    float acc[4][4][4];
    #pragma unroll
    for (int mi = 0; mi < 4; mi++)
        #pragma unroll
        for (int ni = 0; ni < 4; ni++)
            #pragma unroll
            for (int e = 0; e < 4; e++) acc[mi][ni][e] = 0.f;

    const int nC = K >> 6;

    auto issue = [&](int c) {
        const int k0 = c << 6;
        const uint32_t st = sb + (uint32_t)(c % 3) * SZ;
        #pragma unroll
        for (int i = 0; i < 4; i++) {
            const int r = sr[i];
            const uint32_t so = swz((uint32_t)(r * 128 + su[i] * 16));
            const int kk = k0 + su[i] * 8;
            int ga = rowBase + r; if (ga >= M) ga = M - 1;   // clamp: finite garbage, never stored
            const int gb = colBase + r;
            cpa16(st + so, A0 + (size_t)ga * lda + kk);
            if (APL == 2) cpa16(st + 16384 + so, A1 + (size_t)ga * lda + kk);
            cpa16(st + APL * 16384 + so, B0 + (size_t)gb * ldb + kk);
            if (BPL == 2) cpa16(st + APL * 16384 + 16384 + so, B1 + (size_t)gb * ldb + kk);
        }
        CP_COMMIT();
    };

    issue(0);
    if (nC > 1) issue(1);
    for (int c = 0; c < nC; c++) {
        if (c + 2 < nC) { issue(c + 2); CP_WAIT2(); }
        else if (c + 1 < nC) CP_WAIT1();
        else CP_WAIT0();
        __syncthreads();

        const uint32_t st = sb + (uint32_t)(c % 3) * SZ;
        const uint32_t sA0 = st;
        const uint32_t sA1 = st + 16384;
        const uint32_t sB0 = st + APL * 16384;
        const uint32_t sB1 = sB0 + 16384;

        const int aRow16 = lane & 15;
        const int aUhalf = lane >> 4;
        const int bRow   = ((lane >> 4) & 1) * 8 + (lane & 7);
        const int bUhalf = (lane >> 3) & 1;

        #pragma unroll
        for (int ks = 0; ks < 4; ks++) {
            uint32_t a0[4][4], a1[4][4];
            #pragma unroll
            for (int mi = 0; mi < 4; mi++) {
                const int row = warpM * 64 + mi * 16 + aRow16;
                const uint32_t off = swz((uint32_t)(row * 128 + (ks * 2 + aUhalf) * 16));
                ldsm4(a0[mi], sA0 + off);
                if (APL == 2) ldsm4(a1[mi], sA1 + off);
            }
            uint32_t b0[4][2], b1[4][2];
            #pragma unroll
            for (int nb = 0; nb < 2; nb++) {
                const int row = warpN * 32 + nb * 16 + bRow;
                const uint32_t off = swz((uint32_t)(row * 128 + (ks * 2 + bUhalf) * 16));
                uint32_t t[4];
                ldsm4(t, sB0 + off);
                b0[nb * 2][0] = t[0]; b0[nb * 2][1] = t[1];
                b0[nb * 2 + 1][0] = t[2]; b0[nb * 2 + 1][1] = t[3];
                if (BPL == 2) {
                    ldsm4(t, sB1 + off);
                    b1[nb * 2][0] = t[0]; b1[nb * 2][1] = t[1];
                    b1[nb * 2 + 1][0] = t[2]; b1[nb * 2 + 1][1] = t[3];
                }
            }
            #pragma unroll
            for (int mi = 0; mi < 4; mi++)
                #pragma unroll
                for (int ni = 0; ni < 4; ni++) {
                    if (FP16) {
                        mma_f16(acc[mi][ni], a0[mi], b0[ni]);
                        if (APL == 2) mma_f16(acc[mi][ni], a1[mi], b0[ni]);
                        if (BPL == 2) mma_f16(acc[mi][ni], a0[mi], b1[ni]);
                    } else {
                        mma_bf16(acc[mi][ni], a0[mi], b0[ni]);
                        if (APL == 2) mma_bf16(acc[mi][ni], a1[mi], b0[ni]);
                        if (BPL == 2) mma_bf16(acc[mi][ni], a0[mi], b1[ni]);
                    }
                }
        }
        __syncthreads();
    }

    const int lr = lane >> 2;
    const int lc = (lane & 3) * 2;

    if (MODE == 0) {
        #pragma unroll
        for (int mi = 0; mi < 4; mi++)
            #pragma unroll
            for (int ni = 0; ni < 4; ni++) {
                const int r0 = rowBase + warpM * 64 + mi * 16 + lr;
                const int cc = colBase + warpN * 32 + ni * 8 + lc;
                if (r0 < M)
                    *reinterpret_cast<float2*>(&C[co + (size_t)r0 * ldc + cc]) =
                        make_float2(acc[mi][ni][0], acc[mi][ni][1]);
                if (r0 + 8 < M)
                    *reinterpret_cast<float2*>(&C[co + (size_t)(r0 + 8) * ldc + cc]) =
                        make_float2(acc[mi][ni][2], acc[mi][ni][3]);
            }
    } else {
        float* es = reinterpret_cast<float*>(smem);   // 128 x 129 fp32 (aliases stages; synced)
        #pragma unroll
        for (int mi = 0; mi < 4; mi++)
            #pragma unroll
            for (int ni = 0; ni < 4; ni++) {
                const int r0 = warpM * 64 + mi * 16 + lr;
                const int cc = warpN * 32 + ni * 8 + lc;
                es[r0 * 129 + cc]           = acc[mi][ni][0];
                es[r0 * 129 + cc + 1]       = acc[mi][ni][1];
                es[(r0 + 8) * 129 + cc]     = acc[mi][ni][2];
                es[(r0 + 8) * 129 + cc + 1] = acc[mi][ni][3];
            }
        __syncthreads();
        {   // 64-group softmax: 256 threads = 128 rows x 2 groups
            const int r = tid & 127, g = tid >> 7;
            float* p = es + r * 129 + g * 64;
            float m = -1e30f;
            #pragma unroll 4
            for (int i = 0; i < 64; i++) m = fmaxf(m, p[i] * SCALE_F);
            float s = 0.f;
            #pragma unroll 4
            for (int i = 0; i < 64; i++) { float e = __expf(p[i] * SCALE_F - m); p[i] = e; s += e; }
            const float inv = 1.0f / s;
            #pragma unroll 4
            for (int i = 0; i < 64; i++) p[i] *= inv;
        }
        __syncthreads();
        for (int idx = tid; idx < 8192; idx += 256) {   // 128 rows x 64 half2
            const int r = idx >> 6, c2 = (idx & 63) * 2;
            __half2 hv = __floats2half2_rn(es[r * 129 + c2], es[r * 129 + c2 + 1]);
            const size_t o = (size_t)(rowBase + r) * ldc + colBase + c2;
            *reinterpret_cast<__half2*>(Ch + o) = hv;
        }
    }
}

// =================== X -> fp16 single ===================
__global__ void fsplit_f16(const float* __restrict__ src, __half* __restrict__ dst, size_t n)
{
    size_t i = ((size_t)blockIdx.x * blockDim.x + threadIdx.x) * 4;
    if (i >= n) return;
    float4 v = *reinterpret_cast<const float4*>(src + i);
    __half2 p0 = __floats2half2_rn(v.x, v.y);
    __half2 p1 = __floats2half2_rn(v.z, v.w);
    uint2 o;
    o.x = *reinterpret_cast<uint32_t*>(&p0);
    o.y = *reinterpret_cast<uint32_t*>(&p1);
    *reinterpret_cast<uint2*>(dst + i) = o;
}

// =================== X rows t<64 per batch -> bf16 hi/lo compact [B*64, 2048] ===================
__global__ void xsplit64(const float* __restrict__ x, bf16* __restrict__ h, bf16* __restrict__ l)
{
    int idx = blockIdx.x * blockDim.x + threadIdx.x;
    if (idx >= BATCH * 64 * 2048 / 4) return;
    const int e = idx * 4;
    const int c = e & 2047;
    const int row = e >> 11;           // b*64 + t
    const int b = row >> 6, t = row & 63;
    float4 v = *reinterpret_cast<const float4*>(&x[((size_t)(b * SEQ + t)) * CM + c]);
    const size_t o = (size_t)row * CM + c;
    bf16 h0 = __float2bfloat16(v.x), h1 = __float2bfloat16(v.y);
    bf16 h2 = __float2bfloat16(v.z), h3 = __float2bfloat16(v.w);
    h[o] = h0; h[o + 1] = h1; h[o + 2] = h2; h[o + 3] = h3;
    l[o]     = __float2bfloat16(v.x - __bfloat162float(h0));
    l[o + 1] = __float2bfloat16(v.y - __bfloat162float(h1));
    l[o + 2] = __float2bfloat16(v.z - __bfloat162float(h2));
    l[o + 3] = __float2bfloat16(v.w - __bfloat162float(h3));
}

// =================== transpose + bf16 hi/lo split ===================
__global__ void tsplit(const float* __restrict__ src, bf16* __restrict__ dh,
                       bf16* __restrict__ dl, int R, int C,
                       long long sStride, long long dStride)
{
    __shared__ float t[32][33];
    const int z = blockIdx.z;
    src += (long long)z * sStride;
    dh += (long long)z * dStride;
    dl += (long long)z * dStride;
    const int c0 = blockIdx.x * 32, r0 = blockIdx.y * 32;
    const int x = threadIdx.x, y = threadIdx.y;
    #pragma unroll
    for (int j = 0; j < 32; j += 8)
        t[y + j][x] = src[(size_t)(r0 + y + j) * C + c0 + x];
    __syncthreads();
    #pragma unroll
    for (int j = 0; j < 32; j += 8) {
        const float v = t[x][y + j];
        const bf16 h = __float2bfloat16(v);
        const bf16 l = __float2bfloat16(v - __bfloat162float(h));
        const size_t o = (size_t)(c0 + y + j) * R + r0 + x;
        dh[o] = h; dl[o] = l;
    }
}

// =================== transpose + fp16 single ===================
__global__ void tsplit_f16(const float* __restrict__ src, __half* __restrict__ d,
                           int R, int C, long long sStride, long long dStride)
{
    __shared__ float t[32][33];
    const int z = blockIdx.z;
    src += (long long)z * sStride;
    d += (long long)z * dStride;
    const int c0 = blockIdx.x * 32, r0 = blockIdx.y * 32;
    const int x = threadIdx.x, y = threadIdx.y;
    #pragma unroll
    for (int j = 0; j < 32; j += 8)
        t[y + j][x] = src[(size_t)(r0 + y + j) * C + c0 + x];
    __syncthreads();
    #pragma unroll
    for (int j = 0; j < 32; j += 8)
        d[(size_t)(c0 + y + j) * R + r0 + x] = __float2half(t[x][y + j]);
}

// =================== RoPE on g_k : [B, 64, H, D] fp32 ===================
__global__ void rope_kernel(float* __restrict__ k)
{
    int idx = blockIdx.x * blockDim.x + threadIdx.x;
    if (idx >= BATCH * NLAT * NHEAD * (HDIM / 2)) return;
    const int i = idx & 63;
    const int h = (idx >> 6) & 15;
    const int t = (idx >> 10) & 63;
    const int b = idx >> 16;
    const float inv_freq = expf(-(2.0f * i / 128.0f) * 9.210340371976184f);
    float s, c;
    __sincosf((float)t * inv_freq, &s, &c);
    const size_t base = ((((size_t)b * NLAT + t) * NHEAD + h) * HDIM) + 2 * i;
    const float x0 = k[base], x1 = k[base + 1];
    k[base]     = x0 * c - x1 * s;
    k[base + 1] = x0 * s + x1 * c;
}

// =================== small causal attention, outputs bf16 hi/lo ===================
#define ATTN_SMEM ((8192 + 64*129 + 64*129 + 64*65) * 4)
__global__ __launch_bounds__(256, 1) void attn2(
    const float* __restrict__ lq, const float* __restrict__ k, const float* __restrict__ v,
    bf16* __restrict__ ah, bf16* __restrict__ al)
{
    extern __shared__ float s[];
    float* sQ = s;
    float* sK = s + 8192;
    float* sV = sK + 64 * 129;
    float* sS = sV + 64 * 129;
    const int b = blockIdx.x >> 4, h = blockIdx.x & 15;
    const int tid = threadIdx.x;

    for (int i = tid; i < 8192; i += 256) {
        const int t = i >> 7, d = i & 127;
        sQ[i] = lq[(t * 16 + h) * 128 + d];
        const size_t gi = (((size_t)(b * 64 + t)) * 16 + h) * 128 + d;
        sK[t * 129 + d] = k[gi];
        sV[t * 129 + d] = v[gi];
    }
    __syncthreads();

    for (int i = tid; i < 4096; i += 256) {
        const int l = i >> 6, t = i & 63;
        float sc = -1e9f;
        if (t <= l) {
            const float* qp = sQ + l * 128;
            const float* kp = sK + t * 129;
            float a0 = 0.f, a1 = 0.f, a2 = 0.f, a3 = 0.f;
            #pragma unroll
            for (int d = 0; d < 128; d += 4) {
                a0 += qp[d] * kp[d];         a1 += qp[d + 1] * kp[d + 1];
                a2 += qp[d + 2] * kp[d + 2]; a3 += qp[d + 3] * kp[d + 3];
            }
            sc = (a0 + a1 + a2 + a3) * SCALE_F;
        }
        sS[l * 65 + t] = sc;
    }
    __syncthreads();

    if (tid < 64) {
        float* p = sS + tid * 65;
        float m = -1e30f;
        for (int t = 0; t < 64; t++) m = fmaxf(m, p[t]);
        float sum = 0.f;
        for (int t = 0; t < 64; t++) { float e = __expf(p[t] - m); p[t] = e; sum += e; }
        const float inv = 1.0f / sum;
        for (int t = 0; t < 64; t++) p[t] *= inv;
    }
    __syncthreads();

    for (int i = tid; i < 8192; i += 256) {
        const int l = i >> 7, d = i & 127;
        const float* w = sS + l * 65;
        float a0 = 0.f, a1 = 0.f, a2 = 0.f, a3 = 0.f;
        #pragma unroll
        for (int t = 0; t < 64; t += 4) {
            a0 += w[t] * sV[t * 129 + d];
            a1 += w[t + 1] * sV[(t + 1) * 129 + d];
            a2 += w[t + 2] * sV[(t + 2) * 129 + d];
            a3 += w[t + 3] * sV[(t + 3) * 129 + d];
        }
        const float acc = a0 + a1 + a2 + a3;
        const size_t o = ((size_t)(b * 16 + h) * 64 + l) * 128 + d;
        const bf16 hh = __float2bfloat16(acc);
        ah[o] = hh;
        al[o] = __float2bfloat16(acc - __bfloat162float(hh));
    }
}

// =================== launch ===================
extern "C" void kernel_launch(void* const* d_in, const int* in_sizes, int n_in,
                              void* d_out, int out_size)
{
    const float* x  = (const float*)d_in[0];
    const float* lq = (const float*)d_in[1];
    const float* Wk = (const float*)d_in[2];
    const float* Wv = (const float*)d_in[3];
    const float* Wg = (const float*)d_in[4];
    const float* Wp = (const float*)d_in[5];
    float* out = (float*)d_out;

    __half *Xf, *Wgtf, *Ptf, *Gh;
    bf16 *X64h, *X64l, *Wkth, *Wktl, *Wvth, *Wvtl, *Wpth, *Wptl, *ah, *al;
    float *kb, *vb, *Pb;
    cudaGetSymbolAddress((void**)&Xf, g_Xf);
    cudaGetSymbolAddress((void**)&X64h, g_X64h);  cudaGetSymbolAddress((void**)&X64l, g_X64l);
    cudaGetSymbolAddress((void**)&Wkth, g_Wkt_h); cudaGetSymbolAddress((void**)&Wktl, g_Wkt_l);
    cudaGetSymbolAddress((void**)&Wvth, g_Wvt_h); cudaGetSymbolAddress((void**)&Wvtl, g_Wvt_l);
    cudaGetSymbolAddress((void**)&Wpth, g_Wpt_h); cudaGetSymbolAddress((void**)&Wptl, g_Wpt_l);
    cudaGetSymbolAddress((void**)&Wgtf, g_Wgt_f);
    cudaGetSymbolAddress((void**)&kb, g_k);       cudaGetSymbolAddress((void**)&vb, g_v);
    cudaGetSymbolAddress((void**)&ah, g_ah);      cudaGetSymbolAddress((void**)&al, g_al);
    cudaGetSymbolAddress((void**)&Pb, g_P);       cudaGetSymbolAddress((void**)&Ptf, g_Ptf);
    cudaGetSymbolAddress((void**)&Gh, g_Gh);

    // smem sizes: (APL+BPL)*16KB * 3 stages
    const int SM22 = 3 * 4 * 16384;   // 192KB  (bf16x3 kv/P)
    const int SM11 = 3 * 2 * 16384;   //  96KB  (fp16 1-pass gates & out)
    cudaFuncSetAttribute(mm_tc<2,2,0,0>, cudaFuncAttributeMaxDynamicSharedMemorySize, SM22);
    cudaFuncSetAttribute(mm_tc<1,1,2,1>, cudaFuncAttributeMaxDynamicSharedMemorySize, SM11);
    cudaFuncSetAttribute(mm_tc<1,1,0,1>, cudaFuncAttributeMaxDynamicSharedMemorySize, SM11);
    cudaFuncSetAttribute(attn2, cudaFuncAttributeMaxDynamicSharedMemorySize, ATTN_SMEM);

    // 1) X -> fp16 (gates GEMM A); X rows t<64 -> bf16 hi/lo (kv GEMM A)
    fsplit_f16<<<32768, 256>>>(x, Xf, (size_t)16384 * 2048);
    xsplit64<<<512, 256>>>(x, X64h, X64l);
    // 2) weight transposes
    {
        dim3 blk(32, 8);
        tsplit<<<dim3(64, 64, 1), blk>>>(Wk, Wkth, Wktl, 2048, 2048, 0, 0);
        tsplit<<<dim3(64, 64, 1), blk>>>(Wv, Wvth, Wvtl, 2048, 2048, 0, 0);
        tsplit<<<dim3(64, 64, 1), blk>>>(Wp, Wpth, Wptl, 2048, 2048, 0, 0);
        tsplit_f16<<<dim3(32, 64, 1), blk>>>(Wg, Wgtf, 2048, 1024, 0, 0);
    }
    // 3) k/v = x[:, :64] @ Wk/Wv  (bf16x3 exact; M=64 per batch)
    mm_tc<2,2,0,0><<<dim3(16, 1, BATCH), 256, SM22>>>(
        (const uint16_t*)X64h, (const uint16_t*)X64l,
        (const uint16_t*)Wkth, (const uint16_t*)Wktl,
        kb, nullptr,
        64, 2048, 2048, 2048, 2048,
        (long long)64 * CM, 0LL, (long long)NLAT * CM, 1);
    mm_tc<2,2,0,0><<<dim3(16, 1, BATCH), 256, SM22>>>(
        (const uint16_t*)X64h, (const uint16_t*)X64l,
        (const uint16_t*)Wvth, (const uint16_t*)Wvtl,
        vb, nullptr,
        64, 2048, 2048, 2048, 2048,
        (long long)64 * CM, 0LL, (long long)NLAT * CM, 1);
    // 4) RoPE on k
    rope_kernel<<<(BATCH * NLAT * NHEAD * 64 + 255) / 256, 256>>>(kb);
    // 5) attention -> ah/al bf16 hi/lo
    attn2<<<BATCH * NHEAD, 256, ATTN_SMEM>>>(lq, kb, vb, ah, al);
    // 6) P[b,h] = attn[b,h] @ Wp[h*128:(h+1)*128, :]   (bf16x3; z = b*16+h, M=64, K=128)
    mm_tc<2,2,0,0><<<dim3(16, 1, BATCH * NHEAD), 256, SM22>>>(
        (const uint16_t*)ah, (const uint16_t*)al,
        (const uint16_t*)Wpth, (const uint16_t*)Wptl,
        Pb, nullptr,
        64, 128, 128, 2048, 2048,
        (long long)NLAT * HDIM, 128LL, (long long)NLAT * CM, NHEAD);
    // 7) P[b] [1024,2048] -> Pt[b] [2048,1024] fp16
    {
        dim3 blk(32, 8);
        tsplit_f16<<<dim3(64, 32, BATCH), blk>>>(Pb, Ptf, 1024, 2048,
                                                 (long long)HL * CM, (long long)CM * HL);
    }
    // 8) gates = softmax64(x @ Wg * SCALE) -> fp16 (fp16 single-pass + fused epilogue)
    mm_tc<1,1,2,1><<<dim3(8, 128, 1), 256, SM11>>>(
        (const uint16_t*)Xf, nullptr,
        (const uint16_t*)Wgtf, nullptr,
        nullptr, Gh,
        16384, 2048, 2048, 2048, 1024,
        0LL, 0LL, 0LL, 1);
    // 9) out[b] = gates[b] @ Pt[b]^T  (fp16 single-pass both operands)
    mm_tc<1,1,0,1><<<dim3(16, 32, BATCH), 256, SM11>>>(
        (const uint16_t*)Gh, nullptr,
        (const uint16_t*)Ptf, nullptr,
        out, nullptr,
        4096, 1024, 1024, 1024, 2048,
        (long long)SEQ * HL, (long long)CM * HL, (long long)SEQ * CM, 0);
}

// round 13
// speedup vs baseline: 9.0427x; 1.3858x over previous
#include <cuda_runtime.h>
#include <cuda_bf16.h>
#include <cuda_fp16.h>
#include <cstdint>
#include <math.h>

#define BATCH 4
#define SEQ 4096
#define CM 2048
#define NHEAD 16
#define HDIM 128
#define NLAT 64
#define HL 1024
#define SCALE_F 0.08838834764831845f

// ------------------- device scratch (no allocations allowed) -------------------
__device__ __half g_Xf[(size_t)16384 * 2048];        // X fp16
__device__ __half g_Wkt_f[(size_t)2048 * 2048];      // Wk^T fp16
__device__ __half g_Wvt_f[(size_t)2048 * 2048];      // Wv^T fp16
__device__ __half g_Wpt_f[(size_t)2048 * 2048];      // Wp^T fp16
__device__ __half g_Wgt_f[(size_t)1024 * 2048];      // Wg^T fp16
__device__ float  g_k[BATCH * NLAT * CM];            // k fp32 [B*64, 2048]
__device__ float  g_v[BATCH * NLAT * CM];
__device__ __half g_af[BATCH * NHEAD * NLAT * HDIM]; // attn fp16 [B,H,64,128]
__device__ __half g_Ptf[(size_t)BATCH * CM * HL];    // P^T fp16 [B][2048][1024]
__device__ __half g_Gh[(size_t)16384 * 1024];        // gates fp16

// ------------------- helpers (baseline PTX only) -------------------
__device__ __forceinline__ uint32_t smem_u32(const void* p) {
    uint32_t a;
    asm("{ .reg .u64 t; cvta.to.shared.u64 t, %1; cvt.u32.u64 %0, t; }" : "=r"(a) : "l"(p));
    return a;
}
__device__ __forceinline__ void cpa16(uint32_t sdst, const void* gsrc) {
    asm volatile("cp.async.cg.shared.global [%0], [%1], 16;" :: "r"(sdst), "l"(gsrc));
}
#define CP_COMMIT() asm volatile("cp.async.commit_group;" ::: "memory")
#define CP_WAIT2()  asm volatile("cp.async.wait_group 2;" ::: "memory")
#define CP_WAIT1()  asm volatile("cp.async.wait_group 1;" ::: "memory")
#define CP_WAIT0()  asm volatile("cp.async.wait_group 0;" ::: "memory")

__device__ __forceinline__ void ldsm4(uint32_t* r, uint32_t addr) {
    asm volatile("ldmatrix.sync.aligned.m8n8.x4.shared.b16 {%0,%1,%2,%3}, [%4];"
                 : "=r"(r[0]), "=r"(r[1]), "=r"(r[2]), "=r"(r[3]) : "r"(addr));
}
__device__ __forceinline__ void mma_f16(float* c, const uint32_t* a, const uint32_t* b) {
    asm volatile(
        "mma.sync.aligned.m16n8k16.row.col.f32.f16.f16.f32 "
        "{%0,%1,%2,%3}, {%4,%5,%6,%7}, {%8,%9}, {%0,%1,%2,%3};"
        : "+f"(c[0]), "+f"(c[1]), "+f"(c[2]), "+f"(c[3])
        : "r"(a[0]), "r"(a[1]), "r"(a[2]), "r"(a[3]), "r"(b[0]), "r"(b[1]));
}
__device__ __forceinline__ uint32_t swz(uint32_t off) { return off ^ ((off >> 3) & 0x70); }

// =================== fp16 warp-MMA GEMM ===================
// C[M,N] = A[M,K] @ B[N,K]^T, fp16 operands, fp32 accum.
// MODE 0: fp32 C (row-guarded).
// MODE 2: fused 64-group softmax(*SCALE) -> Ch fp16 (ldc applies to Ch).
// MODE 3: P epilogue: write C^T fp16 to Ch as Ptf[b][chan][h*64+l], z=b*16+h, M=64.
// GATH 1: A row index ga -> (ga>>6)*SEQ + (ga&63)  (gather first-64 rows per batch).
// Tile 128x128x64; 256 thr = 8 warps (2M x 4N); 3-stage cp.async; 2 CTA/SM.
#define MM_SMEM (3 * 32768)   // 96KB

template <int MODE, int GATH>
__global__ __launch_bounds__(256, 2)
void mm_tc(const uint16_t* __restrict__ A0, const uint16_t* __restrict__ B0,
           float* __restrict__ C, __half* __restrict__ Ch,
           int M, int K, int lda, int ldb, int ldc,
           long long aStride, long long bStride, long long cStride, int bModulo)
{
    extern __shared__ char smem[];
    const uint32_t sb = smem_u32(smem);

    const int tid = threadIdx.x;
    const int wid = tid >> 5, lane = tid & 31;
    const int warpM = wid >> 2;
    const int warpN = wid & 3;
    const int z = blockIdx.z;
    const int rowBase = blockIdx.y * 128;
    const int colBase = blockIdx.x * 128;

    A0 += (long long)z * aStride;
    B0 += (long long)(bModulo > 0 ? (z % bModulo) : z) * bStride;
    const long long co = (long long)z * cStride;

    int sr[4], su[4];
    #pragma unroll
    for (int i = 0; i < 4; i++) {
        const int q = (i << 8) + tid;
        sr[i] = q >> 3;
        su[i] = q & 7;
    }

    float acc[4][4][4];
    #pragma unroll
    for (int mi = 0; mi < 4; mi++)
        #pragma unroll
        for (int ni = 0; ni < 4; ni++)
            #pragma unroll
            for (int e = 0; e < 4; e++) acc[mi][ni][e] = 0.f;

    const int nC = K >> 6;

    auto issue = [&](int c) {
        const int k0 = c << 6;
        const uint32_t st = sb + (uint32_t)(c % 3) * 32768u;
        #pragma unroll
        for (int i = 0; i < 4; i++) {
            const int r = sr[i];
            const uint32_t so = swz((uint32_t)(r * 128 + su[i] * 16));
            const int kk = k0 + su[i] * 8;
            int ga = rowBase + r; if (ga >= M) ga = M - 1;   // clamp: finite garbage, never stored
            if (GATH) ga = ((ga >> 6) * SEQ) + (ga & 63);
            const int gb = colBase + r;
            cpa16(st + so,         A0 + (size_t)ga * lda + kk);
            cpa16(st + 16384 + so, B0 + (size_t)gb * ldb + kk);
        }
        CP_COMMIT();
    };

    issue(0);
    if (nC > 1) issue(1);
    for (int c = 0; c < nC; c++) {
        if (c + 2 < nC) { issue(c + 2); CP_WAIT2(); }
        else if (c + 1 < nC) CP_WAIT1();
        else CP_WAIT0();
        __syncthreads();

        const uint32_t st = sb + (uint32_t)(c % 3) * 32768u;
        const uint32_t sA0 = st;
        const uint32_t sB0 = st + 16384;

        const int aRow16 = lane & 15;
        const int aUhalf = lane >> 4;
        const int bRow   = ((lane >> 4) & 1) * 8 + (lane & 7);
        const int bUhalf = (lane >> 3) & 1;

        #pragma unroll
        for (int ks = 0; ks < 4; ks++) {
            uint32_t a0[4][4];
            #pragma unroll
            for (int mi = 0; mi < 4; mi++) {
                const int row = warpM * 64 + mi * 16 + aRow16;
                const uint32_t off = swz((uint32_t)(row * 128 + (ks * 2 + aUhalf) * 16));
                ldsm4(a0[mi], sA0 + off);
            }
            uint32_t b0[4][2];
            #pragma unroll
            for (int nb = 0; nb < 2; nb++) {
                const int row = warpN * 32 + nb * 16 + bRow;
                const uint32_t off = swz((uint32_t)(row * 128 + (ks * 2 + bUhalf) * 16));
                uint32_t t[4];
                ldsm4(t, sB0 + off);
                b0[nb * 2][0] = t[0]; b0[nb * 2][1] = t[1];
                b0[nb * 2 + 1][0] = t[2]; b0[nb * 2 + 1][1] = t[3];
            }
            #pragma unroll
            for (int mi = 0; mi < 4; mi++)
                #pragma unroll
                for (int ni = 0; ni < 4; ni++)
                    mma_f16(acc[mi][ni], a0[mi], b0[ni]);
        }
        __syncthreads();
    }

    const int lr = lane >> 2;
    const int lc = (lane & 3) * 2;

    if (MODE == 0) {
        #pragma unroll
        for (int mi = 0; mi < 4; mi++)
            #pragma unroll
            for (int ni = 0; ni < 4; ni++) {
                const int r0 = rowBase + warpM * 64 + mi * 16 + lr;
                const int cc = colBase + warpN * 32 + ni * 8 + lc;
                if (r0 < M)
                    *reinterpret_cast<float2*>(&C[co + (size_t)r0 * ldc + cc]) =
                        make_float2(acc[mi][ni][0], acc[mi][ni][1]);
                if (r0 + 8 < M)
                    *reinterpret_cast<float2*>(&C[co + (size_t)(r0 + 8) * ldc + cc]) =
                        make_float2(acc[mi][ni][2], acc[mi][ni][3]);
            }
    } else {
        // stage tile to padded smem (aliases stages; post-sync)
        float* es = reinterpret_cast<float*>(smem);   // 128 x 129
        #pragma unroll
        for (int mi = 0; mi < 4; mi++)
            #pragma unroll
            for (int ni = 0; ni < 4; ni++) {
                const int r0 = warpM * 64 + mi * 16 + lr;
                const int cc = warpN * 32 + ni * 8 + lc;
                es[r0 * 129 + cc]           = acc[mi][ni][0];
                es[r0 * 129 + cc + 1]       = acc[mi][ni][1];
                es[(r0 + 8) * 129 + cc]     = acc[mi][ni][2];
                es[(r0 + 8) * 129 + cc + 1] = acc[mi][ni][3];
            }
        __syncthreads();

        if (MODE == 2) {
            {   // 64-group softmax: 256 threads = 128 rows x 2 groups
                const int r = tid & 127, g = tid >> 7;
                float* p = es + r * 129 + g * 64;
                float m = -1e30f;
                #pragma unroll 4
                for (int i = 0; i < 64; i++) m = fmaxf(m, p[i] * SCALE_F);
                float s = 0.f;
                #pragma unroll 4
                for (int i = 0; i < 64; i++) { float e = __expf(p[i] * SCALE_F - m); p[i] = e; s += e; }
                const float inv = 1.0f / s;
                #pragma unroll 4
                for (int i = 0; i < 64; i++) p[i] *= inv;
            }
            __syncthreads();
            for (int idx = tid; idx < 8192; idx += 256) {   // 128 rows x 64 half2
                const int r = idx >> 6, c2 = (idx & 63) * 2;
                __half2 hv = __floats2half2_rn(es[r * 129 + c2], es[r * 129 + c2 + 1]);
                const size_t o = (size_t)(rowBase + r) * ldc + colBase + c2;
                *reinterpret_cast<__half2*>(Ch + o) = hv;
            }
        } else {   // MODE 3: transposed P write; valid rows 0..63 (M=64)
            const int b = z >> 4, h = z & 15;
            __half* dst = Ch + (size_t)b * CM * HL + (size_t)colBase * HL + (size_t)h * 64;
            for (int idx = tid; idx < 128 * 32; idx += 256) {
                const int cc = idx >> 5, r2 = (idx & 31) * 2;
                __half2 hv = __floats2half2_rn(es[r2 * 129 + cc], es[(r2 + 1) * 129 + cc]);
                *reinterpret_cast<__half2*>(dst + (size_t)cc * HL + r2) = hv;
            }
        }
    }
}

// =================== X -> fp16 ===================
__global__ void fsplit_f16(const float* __restrict__ src, __half* __restrict__ dst, size_t n)
{
    size_t i = ((size_t)blockIdx.x * blockDim.x + threadIdx.x) * 4;
    if (i >= n) return;
    float4 v = *reinterpret_cast<const float4*>(src + i);
    __half2 p0 = __floats2half2_rn(v.x, v.y);
    __half2 p1 = __floats2half2_rn(v.z, v.w);
    uint2 o;
    o.x = *reinterpret_cast<uint32_t*>(&p0);
    o.y = *reinterpret_cast<uint32_t*>(&p1);
    *reinterpret_cast<uint2*>(dst + i) = o;
}

// =================== transpose -> fp16: src[R,C] fp32 -> d[C,R] fp16 ===================
__global__ void tsplit_f16(const float* __restrict__ src, __half* __restrict__ d,
                           int R, int C)
{
    __shared__ float t[32][33];
    const int c0 = blockIdx.x * 32, r0 = blockIdx.y * 32;
    const int x = threadIdx.x, y = threadIdx.y;   // 32 x 8
    #pragma unroll
    for (int j = 0; j < 32; j += 8)
        t[y + j][x] = src[(size_t)(r0 + y + j) * C + c0 + x];
    __syncthreads();
    #pragma unroll
    for (int j = 0; j < 32; j += 8)
        d[(size_t)(c0 + y + j) * R + r0 + x] = __float2half(t[x][y + j]);
}

// =================== small causal attention with fused RoPE, fp16 out ===================
#define ATTN_SMEM ((8192 + 64*129 + 64*129 + 64*65) * 4)
__global__ __launch_bounds__(256, 1) void attn2(
    const float* __restrict__ lq, const float* __restrict__ k, const float* __restrict__ v,
    __half* __restrict__ af)
{
    extern __shared__ float s[];
    float* sQ = s;               // 64*128
    float* sK = s + 8192;        // 64*129 (padded)
    float* sV = sK + 64 * 129;
    float* sS = sV + 64 * 129;   // 64*65
    const int b = blockIdx.x >> 4, h = blockIdx.x & 15;
    const int tid = threadIdx.x;

    // Q and V plain loads
    for (int i = tid; i < 8192; i += 256) {
        const int t = i >> 7, d = i & 127;
        sQ[i] = lq[(t * 16 + h) * 128 + d];
        sV[t * 129 + d] = v[(((size_t)(b * 64 + t)) * 16 + h) * 128 + d];
    }
    // K load with fused RoPE (pairs 2i, 2i+1)
    for (int i = tid; i < 4096; i += 256) {
        const int t = i >> 6, ip = i & 63;
        const size_t gi = (((size_t)(b * 64 + t)) * 16 + h) * 128 + 2 * ip;
        const float x0 = k[gi], x1 = k[gi + 1];
        const float inv_freq = __expf(-(2.0f * ip / 128.0f) * 9.210340371976184f);
        float sn, cs;
        __sincosf((float)t * inv_freq, &sn, &cs);
        sK[t * 129 + 2 * ip]     = x0 * cs - x1 * sn;
        sK[t * 129 + 2 * ip + 1] = x0 * sn + x1 * cs;
    }
    __syncthreads();

    for (int i = tid; i < 4096; i += 256) {
        const int l = i >> 6, t = i & 63;
        float sc = -1e9f;
        if (t <= l) {
            const float* qp = sQ + l * 128;
            const float* kp = sK + t * 129;
            float a0 = 0.f, a1 = 0.f, a2 = 0.f, a3 = 0.f;
            #pragma unroll
            for (int d = 0; d < 128; d += 4) {
                a0 += qp[d] * kp[d];         a1 += qp[d + 1] * kp[d + 1];
                a2 += qp[d + 2] * kp[d + 2]; a3 += qp[d + 3] * kp[d + 3];
            }
            sc = (a0 + a1 + a2 + a3) * SCALE_F;
        }
        sS[l * 65 + t] = sc;
    }
    __syncthreads();

    if (tid < 64) {
        float* p = sS + tid * 65;
        float m = -1e30f;
        for (int t = 0; t < 64; t++) m = fmaxf(m, p[t]);
        float sum = 0.f;
        for (int t = 0; t < 64; t++) { float e = __expf(p[t] - m); p[t] = e; sum += e; }
        const float inv = 1.0f / sum;
        for (int t = 0; t < 64; t++) p[t] *= inv;
    }
    __syncthreads();

    for (int i = tid; i < 8192; i += 256) {
        const int l = i >> 7, d = i & 127;
        const float* w = sS + l * 65;
        float a0 = 0.f, a1 = 0.f, a2 = 0.f, a3 = 0.f;
        #pragma unroll
        for (int t = 0; t < 64; t += 4) {
            a0 += w[t] * sV[t * 129 + d];
            a1 += w[t + 1] * sV[(t + 1) * 129 + d];
            a2 += w[t + 2] * sV[(t + 2) * 129 + d];
            a3 += w[t + 3] * sV[(t + 3) * 129 + d];
        }
        af[((size_t)(b * 16 + h) * 64 + l) * 128 + d] = __float2half(a0 + a1 + a2 + a3);
    }
}

// =================== launch ===================
extern "C" void kernel_launch(void* const* d_in, const int* in_sizes, int n_in,
                              void* d_out, int out_size)
{
    const float* x  = (const float*)d_in[0];
    const float* lq = (const float*)d_in[1];
    const float* Wk = (const float*)d_in[2];
    const float* Wv = (const float*)d_in[3];
    const float* Wg = (const float*)d_in[4];
    const float* Wp = (const float*)d_in[5];
    float* out = (float*)d_out;

    __half *Xf, *Wktf, *Wvtf, *Wptf, *Wgtf, *af, *Ptf, *Gh;
    float *kb, *vb;
    cudaGetSymbolAddress((void**)&Xf, g_Xf);
    cudaGetSymbolAddress((void**)&Wktf, g_Wkt_f);
    cudaGetSymbolAddress((void**)&Wvtf, g_Wvt_f);
    cudaGetSymbolAddress((void**)&Wptf, g_Wpt_f);
    cudaGetSymbolAddress((void**)&Wgtf, g_Wgt_f);
    cudaGetSymbolAddress((void**)&kb, g_k);
    cudaGetSymbolAddress((void**)&vb, g_v);
    cudaGetSymbolAddress((void**)&af, g_af);
    cudaGetSymbolAddress((void**)&Ptf, g_Ptf);
    cudaGetSymbolAddress((void**)&Gh, g_Gh);

    cudaFuncSetAttribute(mm_tc<0,0>, cudaFuncAttributeMaxDynamicSharedMemorySize, MM_SMEM);
    cudaFuncSetAttribute(mm_tc<0,1>, cudaFuncAttributeMaxDynamicSharedMemorySize, MM_SMEM);
    cudaFuncSetAttribute(mm_tc<2,0>, cudaFuncAttributeMaxDynamicSharedMemorySize, MM_SMEM);
    cudaFuncSetAttribute(mm_tc<3,0>, cudaFuncAttributeMaxDynamicSharedMemorySize, MM_SMEM);
    cudaFuncSetAttribute(attn2, cudaFuncAttributeMaxDynamicSharedMemorySize, ATTN_SMEM);

    // 1) X -> fp16
    fsplit_f16<<<32768, 256>>>(x, Xf, (size_t)16384 * 2048);
    // 2) weight transposes -> fp16
    {
        dim3 blk(32, 8);
        tsplit_f16<<<dim3(64, 64), blk>>>(Wk, Wktf, 2048, 2048);
        tsplit_f16<<<dim3(64, 64), blk>>>(Wv, Wvtf, 2048, 2048);
        tsplit_f16<<<dim3(64, 64), blk>>>(Wp, Wptf, 2048, 2048);
        tsplit_f16<<<dim3(32, 64), blk>>>(Wg, Wgtf, 2048, 1024);
    }
    // 3) k/v = x[:, :64] @ Wk/Wv  (gathered M=256, single GEMM each)
    mm_tc<0,1><<<dim3(16, 2, 1), 256, MM_SMEM>>>(
        (const uint16_t*)Xf, (const uint16_t*)Wktf, kb, nullptr,
        256, 2048, 2048, 2048, 2048, 0LL, 0LL, 0LL, 1);
    mm_tc<0,1><<<dim3(16, 2, 1), 256, MM_SMEM>>>(
        (const uint16_t*)Xf, (const uint16_t*)Wvtf, vb, nullptr,
        256, 2048, 2048, 2048, 2048, 0LL, 0LL, 0LL, 1);
    // 4) attention (RoPE fused) -> af fp16
    attn2<<<BATCH * NHEAD, 256, ATTN_SMEM>>>(lq, kb, vb, af);
    // 5) P^T = (attn[b,h] @ Wp[h*128:(h+1)*128, :])^T  -> Ptf directly (MODE 3)
    mm_tc<3,0><<<dim3(16, 1, BATCH * NHEAD), 256, MM_SMEM>>>(
        (const uint16_t*)af, (const uint16_t*)Wptf, nullptr, Ptf,
        64, 128, 128, 2048, 0,
        (long long)NLAT * HDIM, 128LL, 0LL, NHEAD);
    // 6) gates = softmax64(x @ Wg * SCALE) -> Gh fp16 (fused epilogue)
    mm_tc<2,0><<<dim3(8, 128, 1), 256, MM_SMEM>>>(
        (const uint16_t*)Xf, (const uint16_t*)Wgtf, nullptr, Gh,
        16384, 2048, 2048, 2048, 1024, 0LL, 0LL, 0LL, 1);
    // 7) out[b] = gates[b] @ Ptf[b]^T -> [4096, 2048] fp32
    mm_tc<0,0><<<dim3(16, 32, BATCH), 256, MM_SMEM>>>(
        (const uint16_t*)Gh, (const uint16_t*)Ptf, out, nullptr,
        4096, 1024, 1024, 1024, 2048,
        (long long)SEQ * HL, (long long)CM * HL, (long long)SEQ * CM, 0);
}

// round 16
// speedup vs baseline: 9.7149x; 1.0743x over previous
#include <cuda_runtime.h>
#include <cuda_bf16.h>
#include <cuda_fp16.h>
#include <cstdint>
#include <math.h>

#define BATCH 4
#define SEQ 4096
#define CM 2048
#define NHEAD 16
#define HDIM 128
#define NLAT 64
#define HL 1024
#define SCALE_F 0.08838834764831845f

// ------------------- device scratch (no allocations allowed) -------------------
__device__ __half g_Xf[(size_t)16384 * 2048];        // X fp16
__device__ __half g_Wkt_f[(size_t)2048 * 2048];      // Wk^T fp16
__device__ __half g_Wvt_f[(size_t)2048 * 2048];      // Wv^T fp16
__device__ __half g_Wpt_f[(size_t)2048 * 2048];      // Wp^T fp16
__device__ __half g_Wgt_f[(size_t)1024 * 2048];      // Wg^T fp16
__device__ float  g_k[BATCH * NLAT * CM];            // k fp32 [B*64, 2048]
__device__ float  g_v[BATCH * NLAT * CM];
__device__ __half g_af[BATCH * NHEAD * NLAT * HDIM]; // attn fp16 [B,H,64,128]
__device__ __half g_Ptf[(size_t)BATCH * CM * HL];    // P^T fp16 [B][2048][1024]
__device__ __half g_Gh[(size_t)16384 * 1024];        // gates fp16

// ------------------- helpers (baseline PTX only) -------------------
__device__ __forceinline__ uint32_t smem_u32(const void* p) {
    uint32_t a;
    asm("{ .reg .u64 t; cvta.to.shared.u64 t, %1; cvt.u32.u64 %0, t; }" : "=r"(a) : "l"(p));
    return a;
}
__device__ __forceinline__ void cpa16(uint32_t sdst, const void* gsrc) {
    asm volatile("cp.async.cg.shared.global [%0], [%1], 16;" :: "r"(sdst), "l"(gsrc));
}
#define CP_COMMIT() asm volatile("cp.async.commit_group;" ::: "memory")
#define CP_WAIT2()  asm volatile("cp.async.wait_group 2;" ::: "memory")
#define CP_WAIT1()  asm volatile("cp.async.wait_group 1;" ::: "memory")
#define CP_WAIT0()  asm volatile("cp.async.wait_group 0;" ::: "memory")

__device__ __forceinline__ void ldsm4(uint32_t* r, uint32_t addr) {
    asm volatile("ldmatrix.sync.aligned.m8n8.x4.shared.b16 {%0,%1,%2,%3}, [%4];"
                 : "=r"(r[0]), "=r"(r[1]), "=r"(r[2]), "=r"(r[3]) : "r"(addr));
}
__device__ __forceinline__ void mma_f16(float* c, const uint32_t* a, const uint32_t* b) {
    asm volatile(
        "mma.sync.aligned.m16n8k16.row.col.f32.f16.f16.f32 "
        "{%0,%1,%2,%3}, {%4,%5,%6,%7}, {%8,%9}, {%0,%1,%2,%3};"
        : "+f"(c[0]), "+f"(c[1]), "+f"(c[2]), "+f"(c[3])
        : "r"(a[0]), "r"(a[1]), "r"(a[2]), "r"(a[3]), "r"(b[0]), "r"(b[1]));
}
__device__ __forceinline__ uint32_t swz(uint32_t off) { return off ^ ((off >> 3) & 0x70); }

// =================== fp16 warp-MMA GEMM ===================
// C[M,N] = A[M,K] @ B[N,K]^T, fp16 operands, fp32 accum.
// MODE 0: fp32 C (row-guarded).
// MODE 2: fused 64-group softmax(*SCALE) -> Ch fp16.
// MODE 3: P epilogue: write C^T fp16 to Ch as Ptf[b][chan][h*64+l], z=b*16+h, M=64.
// MODE 4: dual kv: blockIdx.z selects (B0 -> C) vs (B1alt -> C2); A gathered.
// GATH 1: A row index ga -> (ga>>6)*SEQ + (ga&63).
// Tile 128x128x64; 256 thr = 8 warps (2M x 4N); 3-stage cp.async; 2 CTA/SM.
#define MM_SMEM (3 * 32768)   // 96KB

template <int MODE, int GATH>
__global__ __launch_bounds__(256, 2)
void mm_tc(const uint16_t* __restrict__ A0, const uint16_t* __restrict__ B0,
           const uint16_t* __restrict__ B1alt,
           float* __restrict__ C, float* __restrict__ C2, __half* __restrict__ Ch,
           int M, int K, int lda, int ldb, int ldc,
           long long aStride, long long bStride, long long cStride, int bModulo)
{
    extern __shared__ char smem[];
    const uint32_t sb = smem_u32(smem);

    const int tid = threadIdx.x;
    const int wid = tid >> 5, lane = tid & 31;
    const int warpM = wid >> 2;
    const int warpN = wid & 3;
    const int z = blockIdx.z;
    const int rowBase = blockIdx.y * 128;
    const int colBase = blockIdx.x * 128;

    const uint16_t* Bp = B0;
    float* Cp = C;
    long long co = 0;
    if (MODE == 4) {
        if (z) { Bp = B1alt; Cp = C2; }
    } else {
        A0 += (long long)z * aStride;
        Bp += (long long)(bModulo > 0 ? (z % bModulo) : z) * bStride;
        co = (long long)z * cStride;
    }

    int sr[4], su[4];
    #pragma unroll
    for (int i = 0; i < 4; i++) {
        const int q = (i << 8) + tid;
        sr[i] = q >> 3;
        su[i] = q & 7;
    }

    float acc[4][4][4];
    #pragma unroll
    for (int mi = 0; mi < 4; mi++)
        #pragma unroll
        for (int ni = 0; ni < 4; ni++)
            #pragma unroll
            for (int e = 0; e < 4; e++) acc[mi][ni][e] = 0.f;

    const int nC = K >> 6;

    auto issue = [&](int c) {
        const int k0 = c << 6;
        const uint32_t st = sb + (uint32_t)(c % 3) * 32768u;
        #pragma unroll
        for (int i = 0; i < 4; i++) {
            const int r = sr[i];
            const uint32_t so = swz((uint32_t)(r * 128 + su[i] * 16));
            const int kk = k0 + su[i] * 8;
            int ga = rowBase + r; if (ga >= M) ga = M - 1;   // clamp: finite garbage, never stored
            if (GATH) ga = ((ga >> 6) * SEQ) + (ga & 63);
            const int gb = colBase + r;
            cpa16(st + so,         A0 + (size_t)ga * lda + kk);
            cpa16(st + 16384 + so, Bp + (size_t)gb * ldb + kk);
        }
        CP_COMMIT();
    };

    issue(0);
    if (nC > 1) issue(1);
    for (int c = 0; c < nC; c++) {
        if (c + 2 < nC) { issue(c + 2); CP_WAIT2(); }
        else if (c + 1 < nC) CP_WAIT1();
        else CP_WAIT0();
        __syncthreads();

        const uint32_t st = sb + (uint32_t)(c % 3) * 32768u;
        const uint32_t sA0 = st;
        const uint32_t sB0 = st + 16384;

        const int aRow16 = lane & 15;
        const int aUhalf = lane >> 4;
        const int bRow   = ((lane >> 4) & 1) * 8 + (lane & 7);
        const int bUhalf = (lane >> 3) & 1;

        #pragma unroll
        for (int ks = 0; ks < 4; ks++) {
            uint32_t a0[4][4];
            #pragma unroll
            for (int mi = 0; mi < 4; mi++) {
                const int row = warpM * 64 + mi * 16 + aRow16;
                const uint32_t off = swz((uint32_t)(row * 128 + (ks * 2 + aUhalf) * 16));
                ldsm4(a0[mi], sA0 + off);
            }
            uint32_t b0[4][2];
            #pragma unroll
            for (int nb = 0; nb < 2; nb++) {
                const int row = warpN * 32 + nb * 16 + bRow;
                const uint32_t off = swz((uint32_t)(row * 128 + (ks * 2 + bUhalf) * 16));
                uint32_t t[4];
                ldsm4(t, sB0 + off);
                b0[nb * 2][0] = t[0]; b0[nb * 2][1] = t[1];
                b0[nb * 2 + 1][0] = t[2]; b0[nb * 2 + 1][1] = t[3];
            }
            #pragma unroll
            for (int mi = 0; mi < 4; mi++)
                #pragma unroll
                for (int ni = 0; ni < 4; ni++)
                    mma_f16(acc[mi][ni], a0[mi], b0[ni]);
        }
        __syncthreads();
    }

    const int lr = lane >> 2;
    const int lc = (lane & 3) * 2;

    if (MODE == 0 || MODE == 4) {
        #pragma unroll
        for (int mi = 0; mi < 4; mi++)
            #pragma unroll
            for (int ni = 0; ni < 4; ni++) {
                const int r0 = rowBase + warpM * 64 + mi * 16 + lr;
                const int cc = colBase + warpN * 32 + ni * 8 + lc;
                if (r0 < M)
                    *reinterpret_cast<float2*>(&Cp[co + (size_t)r0 * ldc + cc]) =
                        make_float2(acc[mi][ni][0], acc[mi][ni][1]);
                if (r0 + 8 < M)
                    *reinterpret_cast<float2*>(&Cp[co + (size_t)(r0 + 8) * ldc + cc]) =
                        make_float2(acc[mi][ni][2], acc[mi][ni][3]);
            }
    } else {
        // stage tile to padded smem (aliases stages; post-sync)
        float* es = reinterpret_cast<float*>(smem);   // 128 x 129
        #pragma unroll
        for (int mi = 0; mi < 4; mi++)
            #pragma unroll
            for (int ni = 0; ni < 4; ni++) {
                const int r0 = warpM * 64 + mi * 16 + lr;
                const int cc = warpN * 32 + ni * 8 + lc;
                es[r0 * 129 + cc]           = acc[mi][ni][0];
                es[r0 * 129 + cc + 1]       = acc[mi][ni][1];
                es[(r0 + 8) * 129 + cc]     = acc[mi][ni][2];
                es[(r0 + 8) * 129 + cc + 1] = acc[mi][ni][3];
            }
        __syncthreads();

        if (MODE == 2) {
            {   // 64-group softmax: 256 threads = 128 rows x 2 groups
                const int r = tid & 127, g = tid >> 7;
                float* p = es + r * 129 + g * 64;
                float m = -1e30f;
                #pragma unroll 4
                for (int i = 0; i < 64; i++) m = fmaxf(m, p[i] * SCALE_F);
                float s = 0.f;
                #pragma unroll 4
                for (int i = 0; i < 64; i++) { float e = __expf(p[i] * SCALE_F - m); p[i] = e; s += e; }
                const float inv = 1.0f / s;
                #pragma unroll 4
                for (int i = 0; i < 64; i++) p[i] *= inv;
            }
            __syncthreads();
            for (int idx = tid; idx < 8192; idx += 256) {   // 128 rows x 64 half2
                const int r = idx >> 6, c2 = (idx & 63) * 2;
                __half2 hv = __floats2half2_rn(es[r * 129 + c2], es[r * 129 + c2 + 1]);
                const size_t o = (size_t)(rowBase + r) * ldc + colBase + c2;
                *reinterpret_cast<__half2*>(Ch + o) = hv;
            }
        } else {   // MODE 3: transposed P write; valid rows 0..63 (M=64)
            const int b = z >> 4, h = z & 15;
            __half* dst = Ch + (size_t)b * CM * HL + (size_t)colBase * HL + (size_t)h * 64;
            for (int idx = tid; idx < 128 * 32; idx += 256) {
                const int cc = idx >> 5, r2 = (idx & 31) * 2;
                __half2 hv = __floats2half2_rn(es[r2 * 129 + cc], es[(r2 + 1) * 129 + cc]);
                *reinterpret_cast<__half2*>(dst + (size_t)cc * HL + r2) = hv;
            }
        }
    }
}

// =================== fused prep: X->fp16 + 4 weight transposes, one launch ===================
// Flat grid sections:
//   [0, 32768)            : X fp32 -> Xf fp16 (1 float4/thread)
//   [32768, +4096)        : Wk^T   (2048x2048)
//   [36864, +4096)        : Wv^T
//   [40960, +4096)        : Wp^T
//   [45056, +2048)        : Wg^T   (src 2048x1024 -> dst 1024 rows? no: d[C,R], C=1024)
#define PREP_BLOCKS (32768 + 4096 + 4096 + 4096 + 2048)
__global__ __launch_bounds__(256) void prep(
    const float* __restrict__ x, __half* __restrict__ Xf,
    const float* __restrict__ Wk, __half* __restrict__ Wkt,
    const float* __restrict__ Wv, __half* __restrict__ Wvt,
    const float* __restrict__ Wp, __half* __restrict__ Wpt,
    const float* __restrict__ Wg, __half* __restrict__ Wgt)
{
    __shared__ float t[32][33];
    int bid = blockIdx.x;
    const int tid = threadIdx.x;

    if (bid < 32768) {
        const size_t i = ((size_t)bid * 256 + tid) * 4;
        float4 v = *reinterpret_cast<const float4*>(x + i);
        __half2 p0 = __floats2half2_rn(v.x, v.y);
        __half2 p1 = __floats2half2_rn(v.z, v.w);
        uint2 o;
        o.x = *reinterpret_cast<uint32_t*>(&p0);
        o.y = *reinterpret_cast<uint32_t*>(&p1);
        *reinterpret_cast<uint2*>(Xf + i) = o;
        return;
    }
    bid -= 32768;

    const float* src; __half* dst; int R, C;
    if (bid < 4096)      { src = Wk; dst = Wkt; R = 2048; C = 2048; }
    else if (bid < 8192) { src = Wv; dst = Wvt; R = 2048; C = 2048; bid -= 4096; }
    else if (bid < 12288){ src = Wp; dst = Wpt; R = 2048; C = 2048; bid -= 8192; }
    else                 { src = Wg; dst = Wgt; R = 2048; C = 1024; bid -= 12288; }

    const int nbx = C >> 5;
    const int c0 = (bid % nbx) * 32;
    const int r0 = (bid / nbx) * 32;
    const int lx = tid & 31, ly = tid >> 5;   // 32 x 8

    #pragma unroll
    for (int j = 0; j < 32; j += 8)
        t[ly + j][lx] = src[(size_t)(r0 + ly + j) * C + c0 + lx];
    __syncthreads();

    // write d[C,R] as half2 along R (pairs of source rows)
    #pragma unroll
    for (int e = 0; e < 2; e++) {
        const int q = e * 256 + tid;        // 0..511 = 16 row-pairs x 32 cols
        const int rrp = q & 15, cc = q >> 4;
        __half2 hv = __floats2half2_rn(t[2 * rrp][cc], t[2 * rrp + 1][cc]);
        *reinterpret_cast<__half2*>(dst + (size_t)(c0 + cc) * R + r0 + 2 * rrp) = hv;
    }
}

// =================== small causal attention with fused RoPE, fp16 out ===================
#define ATTN_SMEM ((8192 + 64*129 + 64*129 + 64*65) * 4)
__global__ __launch_bounds__(256, 1) void attn2(
    const float* __restrict__ lq, const float* __restrict__ k, const float* __restrict__ v,
    __half* __restrict__ af)
{
    extern __shared__ float s[];
    float* sQ = s;               // 64*128
    float* sK = s + 8192;        // 64*129 (padded)
    float* sV = sK + 64 * 129;
    float* sS = sV + 64 * 129;   // 64*65
    const int b = blockIdx.x >> 4, h = blockIdx.x & 15;
    const int tid = threadIdx.x;

    for (int i = tid; i < 8192; i += 256) {
        const int t = i >> 7, d = i & 127;
        sQ[i] = lq[(t * 16 + h) * 128 + d];
        sV[t * 129 + d] = v[(((size_t)(b * 64 + t)) * 16 + h) * 128 + d];
    }
    for (int i = tid; i < 4096; i += 256) {
        const int t = i >> 6, ip = i & 63;
        const size_t gi = (((size_t)(b * 64 + t)) * 16 + h) * 128 + 2 * ip;
        const float x0 = k[gi], x1 = k[gi + 1];
        const float inv_freq = __expf(-(2.0f * ip / 128.0f) * 9.210340371976184f);
        float sn, cs;
        __sincosf((float)t * inv_freq, &sn, &cs);
        sK[t * 129 + 2 * ip]     = x0 * cs - x1 * sn;
        sK[t * 129 + 2 * ip + 1] = x0 * sn + x1 * cs;
    }
    __syncthreads();

    for (int i = tid; i < 4096; i += 256) {
        const int l = i >> 6, t = i & 63;
        float sc = -1e9f;
        if (t <= l) {
            const float* qp = sQ + l * 128;
            const float* kp = sK + t * 129;
            float a0 = 0.f, a1 = 0.f, a2 = 0.f, a3 = 0.f;
            #pragma unroll
            for (int d = 0; d < 128; d += 4) {
                a0 += qp[d] * kp[d];         a1 += qp[d + 1] * kp[d + 1];
                a2 += qp[d + 2] * kp[d + 2]; a3 += qp[d + 3] * kp[d + 3];
            }
            sc = (a0 + a1 + a2 + a3) * SCALE_F;
        }
        sS[l * 65 + t] = sc;
    }
    __syncthreads();

    if (tid < 64) {
        float* p = sS + tid * 65;
        float m = -1e30f;
        for (int t = 0; t < 64; t++) m = fmaxf(m, p[t]);
        float sum = 0.f;
        for (int t = 0; t < 64; t++) { float e = __expf(p[t] - m); p[t] = e; sum += e; }
        const float inv = 1.0f / sum;
        for (int t = 0; t < 64; t++) p[t] *= inv;
    }
    __syncthreads();

    for (int i = tid; i < 8192; i += 256) {
        const int l = i >> 7, d = i & 127;
        const float* w = sS + l * 65;
        float a0 = 0.f, a1 = 0.f, a2 = 0.f, a3 = 0.f;
        #pragma unroll
        for (int t = 0; t < 64; t += 4) {
            a0 += w[t] * sV[t * 129 + d];
            a1 += w[t + 1] * sV[(t + 1) * 129 + d];
            a2 += w[t + 2] * sV[(t + 2) * 129 + d];
            a3 += w[t + 3] * sV[(t + 3) * 129 + d];
        }
        af[((size_t)(b * 16 + h) * 64 + l) * 128 + d] = __float2half(a0 + a1 + a2 + a3);
    }
}

// =================== launch ===================
extern "C" void kernel_launch(void* const* d_in, const int* in_sizes, int n_in,
                              void* d_out, int out_size)
{
    const float* x  = (const float*)d_in[0];
    const float* lq = (const float*)d_in[1];
    const float* Wk = (const float*)d_in[2];
    const float* Wv = (const float*)d_in[3];
    const float* Wg = (const float*)d_in[4];
    const float* Wp = (const float*)d_in[5];
    float* out = (float*)d_out;

    __half *Xf, *Wktf, *Wvtf, *Wptf, *Wgtf, *af, *Ptf, *Gh;
    float *kb, *vb;
    cudaGetSymbolAddress((void**)&Xf, g_Xf);
    cudaGetSymbolAddress((void**)&Wktf, g_Wkt_f);
    cudaGetSymbolAddress((void**)&Wvtf, g_Wvt_f);
    cudaGetSymbolAddress((void**)&Wptf, g_Wpt_f);
    cudaGetSymbolAddress((void**)&Wgtf, g_Wgt_f);
    cudaGetSymbolAddress((void**)&kb, g_k);
    cudaGetSymbolAddress((void**)&vb, g_v);
    cudaGetSymbolAddress((void**)&af, g_af);
    cudaGetSymbolAddress((void**)&Ptf, g_Ptf);
    cudaGetSymbolAddress((void**)&Gh, g_Gh);

    cudaFuncSetAttribute(mm_tc<0,0>, cudaFuncAttributeMaxDynamicSharedMemorySize, MM_SMEM);
    cudaFuncSetAttribute(mm_tc<4,1>, cudaFuncAttributeMaxDynamicSharedMemorySize, MM_SMEM);
    cudaFuncSetAttribute(mm_tc<2,0>, cudaFuncAttributeMaxDynamicSharedMemorySize, MM_SMEM);
    cudaFuncSetAttribute(mm_tc<3,0>, cudaFuncAttributeMaxDynamicSharedMemorySize, MM_SMEM);
    cudaFuncSetAttribute(attn2, cudaFuncAttributeMaxDynamicSharedMemorySize, ATTN_SMEM);

    // 1) fused prep: X->fp16 + 4 weight transposes
    prep<<<PREP_BLOCKS, 256>>>(x, Xf, Wk, Wktf, Wv, Wvtf, Wp, Wptf, Wg, Wgtf);
    // 2) k & v in ONE launch (MODE 4: z selects Wk->k vs Wv->v; gathered M=256)
    mm_tc<4,1><<<dim3(16, 2, 2), 256, MM_SMEM>>>(
        (const uint16_t*)Xf, (const uint16_t*)Wktf, (const uint16_t*)Wvtf,
        kb, vb, nullptr,
        256, 2048, 2048, 2048, 2048, 0LL, 0LL, 0LL, 1);
    // 3) attention (RoPE fused) -> af fp16
    attn2<<<BATCH * NHEAD, 256, ATTN_SMEM>>>(lq, kb, vb, af);
    // 4) P^T = (attn[b,h] @ Wp[h*128:(h+1)*128, :])^T -> Ptf directly (MODE 3)
    mm_tc<3,0><<<dim3(16, 1, BATCH * NHEAD), 256, MM_SMEM>>>(
        (const uint16_t*)af, (const uint16_t*)Wptf, nullptr,
        nullptr, nullptr, Ptf,
        64, 128, 128, 2048, 0,
        (long long)NLAT * HDIM, 128LL, 0LL, NHEAD);
    // 5) gates = softmax64(x @ Wg * SCALE) -> Gh fp16 (fused epilogue)
    mm_tc<2,0><<<dim3(8, 128, 1), 256, MM_SMEM>>>(
        (const uint16_t*)Xf, (const uint16_t*)Wgtf, nullptr,
        nullptr, nullptr, Gh,
        16384, 2048, 2048, 2048, 1024, 0LL, 0LL, 0LL, 1);
    // 6) out[b] = gates[b] @ Ptf[b]^T -> [4096, 2048] fp32
    mm_tc<0,0><<<dim3(16, 32, BATCH), 256, MM_SMEM>>>(
        (const uint16_t*)Gh, (const uint16_t*)Ptf, nullptr,
        out, nullptr, nullptr,
        4096, 1024, 1024, 1024, 2048,
        (long long)SEQ * HL, (long long)CM * HL, (long long)SEQ * CM, 0);
}